// round 8
// baseline (speedup 1.0000x reference)
#include <cuda_runtime.h>
#include <cuda_fp16.h>
#include <cstdint>
#include <math.h>

#define Bd 8
#define Ld 32
#define HN ((size_t)Bd * Ld * 256 * 256)   // 16777216

// ---------------- device scratch ------------------------------------------
__device__ __align__(16) float g_w[256 * 256];
__device__ __align__(16) __half g_Xh[HN];
__device__ __align__(16) __half g_Xwh[HN];
__device__ __align__(16) __half g_Ech[2 * 256 * 256];
__device__ __align__(16) __half g_Wihh[1024 * 512];
__device__ __align__(16) __half g_Wlinh[256 * 256];
__device__ __align__(16) __half g_Whrh[1024 * 256];
__device__ __align__(16) __half g_Fch[1024 * 512];
__device__ __align__(16) __half g_th[HN];     // LSTM h
__device__ __align__(16) __half g_tbh[HN];    // batchnormed h
__device__ __align__(16) __half g_prh[HN];    // proj
__device__ __align__(16) float g_biasz[1024];
__device__ __align__(16) float g_xproj[HN * 4];
__device__ double g_sum[256], g_ssum[256];
__device__ float g_q[256], g_r0[256];
__device__ unsigned g_rgc[32];
__device__ volatile unsigned g_rgg[32];

// ---------------- helpers --------------------------------------------------
__device__ __forceinline__ uint32_t pack2(float a, float b) {
    __half2 h = __floats2half2_rn(a, b);
    return *(uint32_t*)&h;
}
__device__ __forceinline__ void mma_f16(float* d, const uint32_t* a, const uint32_t* b) {
    asm volatile(
        "mma.sync.aligned.m16n8k16.row.col.f32.f16.f16.f32 "
        "{%0,%1,%2,%3}, {%4,%5,%6,%7}, {%8,%9}, {%0,%1,%2,%3};\n"
        : "+f"(d[0]), "+f"(d[1]), "+f"(d[2]), "+f"(d[3])
        : "r"(a[0]), "r"(a[1]), "r"(a[2]), "r"(a[3]), "r"(b[0]), "r"(b[1]));
}
__device__ __forceinline__ float sigf(float x) { return 1.f / (1.f + expf(-x)); }

__device__ __forceinline__ void cp16(uint32_t s, const void* g) {
    asm volatile("cp.async.cg.shared.global [%0], [%1], 16;" :: "r"(s), "l"(g));
}
#define CPCOMMIT asm volatile("cp.async.commit_group;")
#define CPWAIT1 asm volatile("cp.async.wait_group 1;")
#define CPWAIT0 asm volatile("cp.async.wait_group 0;")

// ---------------- init ------------------------------------------------------
__global__ void k_init(const float* __restrict__ bih, const float* __restrict__ bhh) {
    int i = blockIdx.x * 256 + threadIdx.x;  // grid 4
    g_biasz[i] = bih[i] + bhh[i];
    if (i < 256) { g_sum[i] = 0.0; g_ssum[i] = 0.0; }
    if (i < 32) { g_rgc[i] = 0; g_rgg[i] = 0; }
}

// ---------------- softmax of -dis, row-wise ---------------------------------
__global__ void k_softmax(const float* __restrict__ dis) {
    __shared__ float red[256];
    int o = blockIdx.x, t = threadIdx.x;
    float e = expf(-dis[o * 256 + t]);
    red[t] = e;
    __syncthreads();
    for (int s = 128; s > 0; s >>= 1) {
        if (t < s) red[t] += red[t + s];
        __syncthreads();
    }
    g_w[o * 256 + t] = e / red[0];
}

// ---------------- prep: fp16 operand copies ---------------------------------
__global__ void k_prep(const float4* __restrict__ X, const float4* __restrict__ E1,
                       const float4* __restrict__ E2, const float4* __restrict__ W_ih,
                       const float4* __restrict__ W_hh, const float4* __restrict__ W_lin) {
    long i = (long)blockIdx.x * 256 + threadIdx.x;  // grid 16384
    int nd = (int)(i & 16383);
    float4 x = X[i];
    float4 w = ((const float4*)g_w)[nd];
    ((uint2*)g_Xh)[i] = make_uint2(pack2(x.x, x.y), pack2(x.z, x.w));
    ((uint2*)g_Xwh)[i] = make_uint2(pack2(x.x * w.x, x.y * w.y), pack2(x.z * w.z, x.w * w.w));
    if (i < 32768) {
        float4 e = (i < 16384) ? E1[i] : E2[i - 16384];
        ((uint2*)g_Ech)[i] = make_uint2(pack2(e.x, e.y), pack2(e.z, e.w));
    }
    if (i < 131072) {
        float4 v = W_ih[i];
        ((uint2*)g_Wihh)[i] = make_uint2(pack2(v.x, v.y), pack2(v.z, v.w));
    }
    if (i < 65536) {
        float4 v = W_hh[i];
        ((uint2*)g_Whrh)[i] = make_uint2(pack2(v.x, v.y), pack2(v.z, v.w));
    }
    if (i < 16384) {
        float4 v = W_lin[i];
        ((uint2*)g_Wlinh)[i] = make_uint2(pack2(v.x, v.y), pack2(v.z, v.w));
    }
}

// ---------------- tb = half(q*h + r0) ----------------------------------------
__global__ void k_affine() {
    long i = (long)blockIdx.x * 256 + threadIdx.x;  // grid 32768
    uint32_t u = ((const uint32_t*)g_th)[i];
    __half2 h2 = *(__half2*)&u;
    float2 f = __half22float2(h2);
    int c = (int)((i * 2) & 255);
    f.x = f.x * g_q[c] + g_r0[c];
    f.y = f.y * g_q[c + 1] + g_r0[c + 1];
    ((uint32_t*)g_tbh)[i] = pack2(f.x, f.y);
}

// ---------------- 128x128 fp16 GEMM (unchanged) ------------------------------
template <int AHALF, int HB, int OH>
__global__ void __launch_bounds__(128, 2) kh(
    const __half* __restrict__ A, const __half* __restrict__ A2, long sA, int lda,
    const __half* __restrict__ Bt, long sB, int ldb,
    void* __restrict__ C, long sC, int ldc,
    const float* __restrict__ bias, int K) {
    extern __shared__ uint32_t smu[];

    const int tid = threadIdx.x;
    const int z = blockIdx.z;
    const __half* Ab = A + sA * z;
    const __half* Ab2 = AHALF ? (A2 + sA * z) : nullptr;
    const __half* Bb = Bt + sB * z;
    float* Cf = OH ? nullptr : ((float*)C + sC * z);
    __half* Ch = OH ? ((__half*)C + sC * z) : nullptr;
    const int row0 = blockIdx.x * 128, col0 = blockIdx.y * 128;

    const int lane = tid & 31, wid = tid >> 5;
    const int wm = (wid >> 1) * 64, wn = (wid & 1) * 64;
    const int g = lane >> 2, tq = lane & 3;
    const int rL = tid >> 3, sg4 = (tid & 7) * 4, c8 = (tid & 7) * 8;
    const int nk = K / 64;
    const int STG = 2 * 128 * 36;

    auto load = [&](int s, int k0) {
        const __half* Asrc;
        int kc;
        if (AHALF && k0 >= 256) { Asrc = Ab2; kc = k0 - 256 + c8; }
        else { Asrc = Ab; kc = k0 + c8; }
        uint32_t ab = (uint32_t)__cvta_generic_to_shared(smu + s * STG);
        uint32_t bb = ab + 128 * 36 * 4;
#pragma unroll
        for (int i = 0; i < 8; i++) {
            int r = rL + i * 16;
            cp16(ab + (r * 36 + sg4) * 4, Asrc + (long)(row0 + r) * lda + kc);
        }
#pragma unroll
        for (int i = 0; i < 8; i++) {
            int r = rL + i * 16;
            cp16(bb + (r * 36 + sg4) * 4, Bb + (long)(col0 + r) * ldb + k0 + c8);
        }
        CPCOMMIT;
    };

    float acc[4][8][4] = {};
    load(0, 0);
    load(1, 64);
    for (int kt = 0; kt < nk; kt++) {
        if (kt + 1 < nk) { CPWAIT1; } else { CPWAIT0; }
        __syncthreads();
        const uint32_t* asu = smu + (kt & 1) * STG;
        const uint32_t* bsu = asu + 128 * 36;
#pragma unroll
        for (int kw = 0; kw < 32; kw += 8) {
            uint32_t af[4][4], bf[8][2];
#pragma unroll
            for (int mi = 0; mi < 4; mi++) {
                int base = (wm + mi * 16 + g) * 36 + kw + tq;
                af[mi][0] = asu[base];       af[mi][1] = asu[base + 36 * 8];
                af[mi][2] = asu[base + 4];   af[mi][3] = asu[base + 36 * 8 + 4];
            }
#pragma unroll
            for (int ni = 0; ni < 8; ni++) {
                int base = (wn + ni * 8 + g) * 36 + kw + tq;
                bf[ni][0] = bsu[base];
                bf[ni][1] = bsu[base + 4];
            }
#pragma unroll
            for (int mi = 0; mi < 4; mi++)
#pragma unroll
                for (int ni = 0; ni < 8; ni++) mma_f16(acc[mi][ni], af[mi], bf[ni]);
        }
        __syncthreads();
        if (kt + 2 < nk) load(kt & 1, (kt + 2) * 64);
    }
#pragma unroll
    for (int mi = 0; mi < 4; mi++) {
        int rr = row0 + wm + mi * 16 + g;
#pragma unroll
        for (int ni = 0; ni < 8; ni++) {
            int cc = col0 + wn + ni * 8 + tq * 2;
            float b0 = HB ? bias[cc] : 0.f, b1 = HB ? bias[cc + 1] : 0.f;
            float v0 = acc[mi][ni][0] + b0, v1 = acc[mi][ni][1] + b1;
            float v2 = acc[mi][ni][2] + b0, v3 = acc[mi][ni][3] + b1;
            if (OH) {
                *(uint32_t*)&Ch[(long)rr * ldc + cc] = pack2(v0, v1);
                *(uint32_t*)&Ch[(long)(rr + 8) * ldc + cc] = pack2(v2, v3);
            } else {
                Cf[(long)rr * ldc + cc] = v0;
                Cf[(long)rr * ldc + cc + 1] = v1;
                Cf[(long)(rr + 8) * ldc + cc] = v2;
                Cf[(long)(rr + 8) * ldc + cc + 1] = v3;
            }
        }
    }
}

// ---------------- row-group barrier (4 blocks) -------------------------------
__device__ __forceinline__ void rgbar(int rg, unsigned& mygen) {
    __syncthreads();
    if (threadIdx.x == 0) {
        __threadfence();
        unsigned old = atomicAdd(&g_rgc[rg], 1u);
        if (old == 3u) {
            g_rgc[rg] = 0;
            __threadfence();
            atomicAdd((unsigned*)&g_rgg[rg], 1u);
        } else {
            while (g_rgg[rg] <= mygen) {}
        }
        __threadfence();
    }
    __syncthreads();
    mygen++;
}

// ---------------- persistent LSTM: resident Whh, register Xp -----------------
// grid 128 = 32 row-groups(64 rows) x 4 m-tiles(64). 256 thr.
// Only the 4 blocks of a row-group synchronize (h dependency is group-local).
// xproj gate values loaded straight into registers (overlap A-load + MMA).
__global__ void __launch_bounds__(256) k_lstm() {
    extern __shared__ uint32_t smL[];
    uint32_t* Bs = smL;                          // 256 x 128 u32 (swizzled)
    uint32_t* As = smL + 256 * 128;              // 64 x 128 u32 (swizzled)

    const int tid = threadIdx.x;
    const int bid = blockIdx.x;
    const int rg = bid >> 2;
    const int rows0 = rg * 64, m0 = (bid & 3) * 64;
    const int b = rows0 >> 8, n0 = rows0 & 255;
    const int lane = tid & 31, wid = tid >> 5;
    const int g = lane >> 2, tq = lane & 3;
    const int wr = (wid >> 1) * 16;
    const int cbase = (wid & 1) * 128;
    const int r0 = wr + g, r1 = wr + g + 8;
    const int mloc0 = (wid & 1) * 32 + tq * 2;   // + ni2*8

    const uint32_t bsb = (uint32_t)__cvta_generic_to_shared(Bs);
    const uint32_t asb = (uint32_t)__cvta_generic_to_shared(As);

    // ---- preload gathered Whh slice (once) ----
#pragma unroll
    for (int w = 0; w < 32; w++) {
        int idx = tid + w * 256;
        int c = idx >> 5, s = idx & 31;
        int n = c & 127, nw = c >> 7;
        int wrow = (n >> 5) * 256 + m0 + nw * 32 + (n & 31);
        cp16(bsb + (c * 128 + ((s ^ (c & 7)) << 2)) * 4,
             g_Whrh + (long)wrow * 256 + s * 8);
    }
    CPCOMMIT; CPWAIT0;
    __syncthreads();

    float creg[16];
#pragma unroll
    for (int i = 0; i < 16; i++) creg[i] = 0.f;
    unsigned mygen = 0;

    for (int t = 0; t < Ld; t++) {
        const long xz = ((long)b * Ld + t) * 256;

        // A = h_{t-1} (swizzled)
        if (t > 0) {
            const __half* Ab = g_th + (((long)b * Ld + (t - 1)) * 256 + n0) * 256;
#pragma unroll
            for (int w = 0; w < 8; w++) {
                int idx = tid + w * 256;
                int r = idx >> 5, s = idx & 31;
                cp16(asb + (r * 128 + ((s ^ (r & 7)) << 2)) * 4,
                     Ab + (long)r * 256 + s * 8);
            }
            CPCOMMIT;
        }

        // xproj gate values -> registers (independent of h; overlaps everything)
        float2 xv[4][2][4];   // [ni2][rs][gate]
#pragma unroll
        for (int ni2 = 0; ni2 < 4; ni2++) {
            const int mloc = mloc0 + ni2 * 8;
#pragma unroll
            for (int rs = 0; rs < 2; rs++) {
                const int lr = rs ? r1 : r0;
                const float* base = g_xproj + (xz + n0 + lr) * 1024 + m0 + mloc;
#pragma unroll
                for (int gate = 0; gate < 4; gate++)
                    xv[ni2][rs][gate] = *(const float2*)(base + gate * 256);
            }
        }

        float acc[16][4] = {};
        if (t > 0) {
            CPWAIT0;
            __syncthreads();
#pragma unroll
            for (int j = 0; j < 16; j++) {
                const int x0 = (((2 * j) ^ g) << 2) + tq;
                const int x1 = (((2 * j + 1) ^ g) << 2) + tq;
                uint32_t af[4];
                af[0] = As[r0 * 128 + x0];
                af[1] = As[r1 * 128 + x0];
                af[2] = As[r0 * 128 + x1];
                af[3] = As[r1 * 128 + x1];
#pragma unroll
                for (int ni = 0; ni < 16; ni++) {
                    int c = cbase + ni * 8 + g;
                    uint32_t bf[2];
                    bf[0] = Bs[c * 128 + x0];
                    bf[1] = Bs[c * 128 + x1];
                    mma_f16(acc[ni], af, bf);
                }
            }
        }

        // gates straight from registers
#pragma unroll
        for (int ni2 = 0; ni2 < 4; ni2++) {
            const int mloc = mloc0 + ni2 * 8;
#pragma unroll
            for (int rs = 0; rs < 2; rs++) {
                const int lr = rs ? r1 : r0;
                float hv[2];
#pragma unroll
                for (int col = 0; col < 2; col++) {
                    int ai = rs * 2 + col;
                    float xi = col ? xv[ni2][rs][0].y : xv[ni2][rs][0].x;
                    float xf = col ? xv[ni2][rs][1].y : xv[ni2][rs][1].x;
                    float xg = col ? xv[ni2][rs][2].y : xv[ni2][rs][2].x;
                    float xo = col ? xv[ni2][rs][3].y : xv[ni2][rs][3].x;
                    float zi = acc[ni2][ai] + xi;
                    float zf = acc[4 + ni2][ai] + xf;
                    float zg = acc[8 + ni2][ai] + xg;
                    float zo = acc[12 + ni2][ai] + xo;
                    int k = ni2 * 4 + ai;
                    float cc = sigf(zf) * creg[k] + sigf(zi) * tanhf(zg);
                    creg[k] = cc;
                    hv[col] = sigf(zo) * tanhf(cc);
                }
                *(uint32_t*)&g_th[(xz + n0 + lr) * 256 + m0 + mloc] = pack2(hv[0], hv[1]);
            }
        }
        if (t < Ld - 1) rgbar(rg, mygen);
    }
}

// ---------------- BN stats over g_th ------------------------------------------
__global__ void k_stats() {
    int m = threadIdx.x;
    long base = (long)blockIdx.x * 65536;    // grid 256 (b,l) slices
    float s = 0.f, ss = 0.f;
#pragma unroll 4
    for (int n = 0; n < 256; n++) {
        float v = __half2float(g_th[base + (long)n * 256 + m]);
        s += v; ss += v * v;
    }
    atomicAdd(&g_sum[m], (double)s);
    atomicAdd(&g_ssum[m], (double)ss);
}

// ---------------- BN finalize -------------------------------------------------
__global__ void k_finalize(const float* __restrict__ gamma, const float* __restrict__ beta) {
    int m = threadIdx.x;
    double mu = g_sum[m] / 65536.0;
    double var = g_ssum[m] / 65536.0 - mu * mu;
    float q = gamma[m] * (float)(1.0 / sqrt(var + 1e-5));
    g_q[m] = q;
    g_r0[m] = beta[m] - (float)mu * q;
}

// ---------------- launch ------------------------------------------------------
extern "C" void kernel_launch(void* const* d_in, const int* in_sizes, int n_in,
                              void* d_out, int out_size) {
    const float* X     = (const float*)d_in[0];
    const float* dis   = (const float*)d_in[1];
    const float* E1    = (const float*)d_in[2];
    const float* E2    = (const float*)d_in[3];
    const float* W_ih  = (const float*)d_in[4];
    const float* W_hh  = (const float*)d_in[5];
    const float* b_ih  = (const float*)d_in[6];
    const float* b_hh  = (const float*)d_in[7];
    const float* gamma = (const float*)d_in[8];
    const float* beta  = (const float*)d_in[9];
    const float* W_lin = (const float*)d_in[10];
    const float* b_lin = (const float*)d_in[11];
    float* out = (float*)d_out;

    const int GSMEM = 2 * 2 * 128 * 36 * 4;       // 73728 B
    const int LSMEM = (256 * 128 + 64 * 128) * 4; // 163840 B

    cudaFuncSetAttribute(kh<0, 0, 1>, cudaFuncAttributeMaxDynamicSharedMemorySize, GSMEM);
    cudaFuncSetAttribute(kh<1, 1, 0>, cudaFuncAttributeMaxDynamicSharedMemorySize, GSMEM);
    cudaFuncSetAttribute(kh<0, 1, 1>, cudaFuncAttributeMaxDynamicSharedMemorySize, GSMEM);
    cudaFuncSetAttribute(kh<0, 0, 0>, cudaFuncAttributeMaxDynamicSharedMemorySize, GSMEM);
    cudaFuncSetAttribute(k_lstm, cudaFuncAttributeMaxDynamicSharedMemorySize, LSMEM);

    __half *pXh, *pXwh, *pEch, *pWihh, *pWlinh, *pFch, *pTbh, *pPrh;
    float *pBiasz, *pXproj;
    cudaGetSymbolAddress((void**)&pXh, g_Xh);
    cudaGetSymbolAddress((void**)&pXwh, g_Xwh);
    cudaGetSymbolAddress((void**)&pEch, g_Ech);
    cudaGetSymbolAddress((void**)&pWihh, g_Wihh);
    cudaGetSymbolAddress((void**)&pWlinh, g_Wlinh);
    cudaGetSymbolAddress((void**)&pFch, g_Fch);
    cudaGetSymbolAddress((void**)&pTbh, g_tbh);
    cudaGetSymbolAddress((void**)&pPrh, g_prh);
    cudaGetSymbolAddress((void**)&pBiasz, g_biasz);
    cudaGetSymbolAddress((void**)&pXproj, g_xproj);

    k_init<<<4, 256>>>(b_ih, b_hh);
    k_softmax<<<256, 256>>>(dis);
    k_prep<<<16384, 256>>>((const float4*)X, (const float4*)E1, (const float4*)E2,
                           (const float4*)W_ih, (const float4*)W_hh, (const float4*)W_lin);

    // Fcat
    kh<0, 0, 1><<<dim3(8, 2, 2), 128, GSMEM>>>(
        pWihh, nullptr, 256, 512, pEch, 65536, 256,
        pFch, 256, 512, nullptr, 256);

    // xproj = [Xh | Xwh] @ Fcat^T + biasz (K=512), fp32 out
    kh<1, 1, 0><<<dim3(2, 8, 256), 128, GSMEM>>>(
        pXh, pXwh, 65536, 256, pFch, 0, 512,
        pXproj, 262144, 1024, pBiasz, 512);

    // persistent LSTM (resident Whh, register gates, row-group sync)
    k_lstm<<<128, 256, LSMEM>>>();

    k_stats<<<256, 256>>>();
    k_finalize<<<1, 256>>>(gamma, beta);
    k_affine<<<32768, 256>>>();

    // proj = tb @ Wlin^T + b_lin (half out)
    kh<0, 1, 1><<<dim3(2, 2, 256), 128, GSMEM>>>(
        pTbh, nullptr, 65536, 256, pWlinh, 0, 256,
        pPrh, 65536, 256, b_lin, 256);

    // out = proj @ tb^T (fp32 out)
    kh<0, 0, 0><<<dim3(2, 2, 256), 128, GSMEM>>>(
        pPrh, nullptr, 65536, 256, pTbh, 65536, 256,
        out, 65536, 256, nullptr, 256);
}

// round 9
// speedup vs baseline: 1.0007x; 1.0007x over previous
#include <cuda_runtime.h>
#include <cuda_fp16.h>
#include <cstdint>
#include <math.h>

#define Bd 8
#define Ld 32
#define HN ((size_t)Bd * Ld * 256 * 256)   // 16777216

// ---------------- device scratch ------------------------------------------
__device__ __align__(16) float g_w[256 * 256];
__device__ __align__(16) __half g_Xh[HN];
__device__ __align__(16) __half g_Xwh[HN];
__device__ __align__(16) __half g_Ech[2 * 256 * 256];
__device__ __align__(16) __half g_Wihh[1024 * 512];
__device__ __align__(16) __half g_Wlinh[256 * 256];
__device__ __align__(16) __half g_Whrh[1024 * 256];
__device__ __align__(16) __half g_Fch[1024 * 512];
__device__ __align__(16) __half g_th[HN];     // LSTM h
__device__ __align__(16) __half g_tbh[HN];    // batchnormed h
__device__ __align__(16) __half g_prh[HN];    // proj
__device__ __align__(16) float g_biasz[1024];
__device__ __align__(16) float g_xproj[HN * 4];
__device__ double g_sum[256], g_ssum[256];
__device__ float g_q[256], g_r0[256];
__device__ unsigned g_barcnt;
__device__ volatile unsigned g_bargen;

// ---------------- helpers --------------------------------------------------
__device__ __forceinline__ uint32_t pack2(float a, float b) {
    __half2 h = __floats2half2_rn(a, b);
    return *(uint32_t*)&h;
}
__device__ __forceinline__ void mma_f16(float* d, const uint32_t* a, const uint32_t* b) {
    asm volatile(
        "mma.sync.aligned.m16n8k16.row.col.f32.f16.f16.f32 "
        "{%0,%1,%2,%3}, {%4,%5,%6,%7}, {%8,%9}, {%0,%1,%2,%3};\n"
        : "+f"(d[0]), "+f"(d[1]), "+f"(d[2]), "+f"(d[3])
        : "r"(a[0]), "r"(a[1]), "r"(a[2]), "r"(a[3]), "r"(b[0]), "r"(b[1]));
}
__device__ __forceinline__ void ldsm4(uint32_t& r0, uint32_t& r1, uint32_t& r2,
                                      uint32_t& r3, uint32_t addr) {
    asm volatile("ldmatrix.sync.aligned.m8n8.x4.shared.b16 {%0,%1,%2,%3}, [%4];"
                 : "=r"(r0), "=r"(r1), "=r"(r2), "=r"(r3) : "r"(addr));
}
__device__ __forceinline__ float sigf(float x) { return 1.f / (1.f + expf(-x)); }

__device__ __forceinline__ void cp16(uint32_t s, const void* g) {
    asm volatile("cp.async.cg.shared.global [%0], [%1], 16;" :: "r"(s), "l"(g));
}
#define CPCOMMIT asm volatile("cp.async.commit_group;")
#define CPWAITG1 asm volatile("cp.async.wait_group 1;")
#define CPWAIT1 asm volatile("cp.async.wait_group 1;")
#define CPWAIT0 asm volatile("cp.async.wait_group 0;")

// ---------------- init ------------------------------------------------------
__global__ void k_init(const float* __restrict__ bih, const float* __restrict__ bhh) {
    int i = blockIdx.x * 256 + threadIdx.x;  // grid 4
    g_biasz[i] = bih[i] + bhh[i];
    if (i < 256) { g_sum[i] = 0.0; g_ssum[i] = 0.0; }
    if (i == 0) { g_barcnt = 0; g_bargen = 0; }
}

// ---------------- softmax of -dis, row-wise ---------------------------------
__global__ void k_softmax(const float* __restrict__ dis) {
    __shared__ float red[256];
    int o = blockIdx.x, t = threadIdx.x;
    float e = expf(-dis[o * 256 + t]);
    red[t] = e;
    __syncthreads();
    for (int s = 128; s > 0; s >>= 1) {
        if (t < s) red[t] += red[t + s];
        __syncthreads();
    }
    g_w[o * 256 + t] = e / red[0];
}

// ---------------- prep: fp16 operand copies ---------------------------------
__global__ void k_prep(const float4* __restrict__ X, const float4* __restrict__ E1,
                       const float4* __restrict__ E2, const float4* __restrict__ W_ih,
                       const float4* __restrict__ W_hh, const float4* __restrict__ W_lin) {
    long i = (long)blockIdx.x * 256 + threadIdx.x;  // grid 16384
    int nd = (int)(i & 16383);
    float4 x = X[i];
    float4 w = ((const float4*)g_w)[nd];
    ((uint2*)g_Xh)[i] = make_uint2(pack2(x.x, x.y), pack2(x.z, x.w));
    ((uint2*)g_Xwh)[i] = make_uint2(pack2(x.x * w.x, x.y * w.y), pack2(x.z * w.z, x.w * w.w));
    if (i < 32768) {
        float4 e = (i < 16384) ? E1[i] : E2[i - 16384];
        ((uint2*)g_Ech)[i] = make_uint2(pack2(e.x, e.y), pack2(e.z, e.w));
    }
    if (i < 131072) {
        float4 v = W_ih[i];
        ((uint2*)g_Wihh)[i] = make_uint2(pack2(v.x, v.y), pack2(v.z, v.w));
    }
    if (i < 65536) {
        float4 v = W_hh[i];
        ((uint2*)g_Whrh)[i] = make_uint2(pack2(v.x, v.y), pack2(v.z, v.w));
    }
    if (i < 16384) {
        float4 v = W_lin[i];
        ((uint2*)g_Wlinh)[i] = make_uint2(pack2(v.x, v.y), pack2(v.z, v.w));
    }
}

// ---------------- tb = half(q*h + r0) ----------------------------------------
__global__ void k_affine() {
    long i = (long)blockIdx.x * 256 + threadIdx.x;  // grid 32768
    uint32_t u = ((const uint32_t*)g_th)[i];
    __half2 h2 = *(__half2*)&u;
    float2 f = __half22float2(h2);
    int c = (int)((i * 2) & 255);
    f.x = f.x * g_q[c] + g_r0[c];
    f.y = f.y * g_q[c + 1] + g_r0[c + 1];
    ((uint32_t*)g_tbh)[i] = pack2(f.x, f.y);
}

// ---------------- 128x128 fp16 GEMM with ldmatrix fragments ------------------
// Smem tile: 128 rows x 128 bytes (64 halves/K-chunk), XOR sector swizzle:
// store row r sector s at (s ^ (r&7)); ldmatrix reads are conflict-free.
template <int AHALF, int HB, int OH>
__global__ void __launch_bounds__(128, 2) kh(
    const __half* __restrict__ A, const __half* __restrict__ A2, long sA, int lda,
    const __half* __restrict__ Bt, long sB, int ldb,
    void* __restrict__ C, long sC, int ldc,
    const float* __restrict__ bias, int K) {
    extern __shared__ uint32_t smu[];   // 2 stages x 32KB (A 16K + B 16K)
    const uint32_t sbase = (uint32_t)__cvta_generic_to_shared(smu);

    const int tid = threadIdx.x;
    const int z = blockIdx.z;
    const __half* Ab = A + sA * z;
    const __half* Ab2 = AHALF ? (A2 + sA * z) : nullptr;
    const __half* Bb = Bt + sB * z;
    float* Cf = OH ? nullptr : ((float*)C + sC * z);
    __half* Ch = OH ? ((__half*)C + sC * z) : nullptr;
    const int row0 = blockIdx.x * 128, col0 = blockIdx.y * 128;

    const int lane = tid & 31, wid = tid >> 5;
    const int wm = (wid >> 1) * 64, wn = (wid & 1) * 64;
    const int g = lane >> 2, tq = lane & 3;
    const int rL = tid >> 3, sec = tid & 7;
    const int nk = K / 64;

    // ldmatrix lane geometry
    const int g2 = lane >> 3, lr = lane & 7;
    const int aoff = (g2 & 1) * 8 + lr, aksel = g2 >> 1;       // A tile order a0..a3
    const int boff = (g2 >> 1) * 8 + lr, bksel = g2 & 1;       // B pair order

    auto load = [&](int s, int k0) {
        const __half* Asrc;
        int kc;
        if (AHALF && k0 >= 256) { Asrc = Ab2; kc = k0 - 256 + sec * 8; }
        else { Asrc = Ab; kc = k0 + sec * 8; }
        uint32_t ab = sbase + s * 65536;
        uint32_t bb = ab + 16384;
#pragma unroll
        for (int i = 0; i < 8; i++) {
            int r = rL + i * 16;
            cp16(ab + r * 128 + ((sec ^ (r & 7)) * 16),
                 Asrc + (long)(row0 + r) * lda + kc);
        }
#pragma unroll
        for (int i = 0; i < 8; i++) {
            int r = rL + i * 16;
            cp16(bb + r * 128 + ((sec ^ (r & 7)) * 16),
                 Bb + (long)(col0 + r) * ldb + k0 + sec * 8);
        }
        CPCOMMIT;
    };

    float acc[4][8][4] = {};
    load(0, 0);
    load(1, 64);
    for (int kt = 0; kt < nk; kt++) {
        if (kt + 1 < nk) { CPWAIT1; } else { CPWAIT0; }
        __syncthreads();
        const uint32_t ab = sbase + (kt & 1) * 65536;
        const uint32_t bb = ab + 16384;
#pragma unroll
        for (int kw = 0; kw < 4; kw++) {          // 4 k16 groups per chunk
            uint32_t af[4][4], bf[8][2];
#pragma unroll
            for (int mi = 0; mi < 4; mi++) {
                int rr = wm + mi * 16 + aoff;
                uint32_t addr = ab + rr * 128 + (((kw * 2 + aksel) ^ lr) * 16);
                ldsm4(af[mi][0], af[mi][1], af[mi][2], af[mi][3], addr);
            }
#pragma unroll
            for (int np = 0; np < 4; np++) {      // ni pairs
                int rr = wn + np * 16 + boff;
                uint32_t addr = bb + rr * 128 + (((kw * 2 + bksel) ^ lr) * 16);
                ldsm4(bf[2 * np][0], bf[2 * np][1], bf[2 * np + 1][0], bf[2 * np + 1][1], addr);
            }
#pragma unroll
            for (int mi = 0; mi < 4; mi++)
#pragma unroll
                for (int ni = 0; ni < 8; ni++) mma_f16(acc[mi][ni], af[mi], bf[ni]);
        }
        __syncthreads();
        if (kt + 2 < nk) load(kt & 1, (kt + 2) * 64);
    }
#pragma unroll
    for (int mi = 0; mi < 4; mi++) {
        int rr = row0 + wm + mi * 16 + g;
#pragma unroll
        for (int ni = 0; ni < 8; ni++) {
            int cc = col0 + wn + ni * 8 + tq * 2;
            float b0 = HB ? bias[cc] : 0.f, b1 = HB ? bias[cc + 1] : 0.f;
            float v0 = acc[mi][ni][0] + b0, v1 = acc[mi][ni][1] + b1;
            float v2 = acc[mi][ni][2] + b0, v3 = acc[mi][ni][3] + b1;
            if (OH) {
                *(uint32_t*)&Ch[(long)rr * ldc + cc] = pack2(v0, v1);
                *(uint32_t*)&Ch[(long)(rr + 8) * ldc + cc] = pack2(v2, v3);
            } else {
                Cf[(long)rr * ldc + cc] = v0;
                Cf[(long)rr * ldc + cc + 1] = v1;
                Cf[(long)(rr + 8) * ldc + cc] = v2;
                Cf[(long)(rr + 8) * ldc + cc + 1] = v3;
            }
        }
    }
}

// ---------------- grid barrier ----------------------------------------------
__device__ __forceinline__ void gridbar(unsigned nb, unsigned& mygen) {
    __syncthreads();
    if (threadIdx.x == 0) {
        __threadfence();
        unsigned old = atomicAdd(&g_barcnt, 1u);
        if (old == nb - 1) {
            g_barcnt = 0;
            __threadfence();
            atomicAdd((unsigned*)&g_bargen, 1u);
        } else {
            while (g_bargen <= mygen) {}
        }
        __threadfence();
    }
    __syncthreads();
    mygen++;
}

// ---------------- persistent LSTM (R6 form: resident Whh, smem Xp) -----------
__global__ void __launch_bounds__(256) k_lstm() {
    extern __shared__ uint32_t smL[];
    uint32_t* Bs = smL;                          // 256 x 128 u32 (swizzled)
    uint32_t* As = smL + 256 * 128;              // 64 x 128 u32 (swizzled)
    float* Xp = (float*)(smL + 256 * 128 + 64 * 128);  // 64 x 260 f32

    const int tid = threadIdx.x;
    const int bid = blockIdx.x;
    const int rows0 = (bid >> 2) * 64, m0 = (bid & 3) * 64;
    const int b = rows0 >> 8, n0 = rows0 & 255;
    const int lane = tid & 31, wid = tid >> 5;
    const int g = lane >> 2, tq = lane & 3;
    const int wr = (wid >> 1) * 16;
    const int cbase = (wid & 1) * 128;
    const int r0 = wr + g, r1 = wr + g + 8;

    const uint32_t bsb = (uint32_t)__cvta_generic_to_shared(Bs);
    const uint32_t asb = (uint32_t)__cvta_generic_to_shared(As);
    const uint32_t xpb = (uint32_t)__cvta_generic_to_shared(Xp);

    // ---- preload gathered Whh slice (once) ----
#pragma unroll
    for (int w = 0; w < 32; w++) {
        int idx = tid + w * 256;
        int c = idx >> 5, s = idx & 31;
        int n = c & 127, nw = c >> 7;
        int wrow = (n >> 5) * 256 + m0 + nw * 32 + (n & 31);
        cp16(bsb + (c * 128 + ((s ^ (c & 7)) << 2)) * 4,
             g_Whrh + (long)wrow * 256 + s * 8);
    }
    CPCOMMIT; CPWAIT0;
    __syncthreads();

    float creg[16];
#pragma unroll
    for (int i = 0; i < 16; i++) creg[i] = 0.f;
    unsigned mygen = 0;

    for (int t = 0; t < Ld; t++) {
        const long xz = ((long)b * Ld + t) * 256;

        if (t > 0) {
            const __half* Ab = g_th + (((long)b * Ld + (t - 1)) * 256 + n0) * 256;
#pragma unroll
            for (int w = 0; w < 8; w++) {
                int idx = tid + w * 256;
                int r = idx >> 5, s = idx & 31;
                cp16(asb + (r * 128 + ((s ^ (r & 7)) << 2)) * 4,
                     Ab + (long)r * 256 + s * 8);
            }
        }
        CPCOMMIT;
#pragma unroll
        for (int w = 0; w < 16; w++) {
            int idx = tid + w * 256;
            int r = idx >> 6, s = idx & 63;
            int gate = s >> 4, ms = (s & 15) * 4;
            cp16(xpb + (r * 260 + gate * 64 + ms) * 4,
                 g_xproj + (xz + n0 + r) * 1024 + gate * 256 + m0 + ms);
        }
        CPCOMMIT;
        CPWAITG1;
        __syncthreads();

        float acc[16][4] = {};
        if (t > 0) {
#pragma unroll
            for (int j = 0; j < 16; j++) {
                const int x0 = (((2 * j) ^ g) << 2) + tq;
                const int x1 = (((2 * j + 1) ^ g) << 2) + tq;
                uint32_t af[4];
                af[0] = As[r0 * 128 + x0];
                af[1] = As[r1 * 128 + x0];
                af[2] = As[r0 * 128 + x1];
                af[3] = As[r1 * 128 + x1];
#pragma unroll
                for (int ni = 0; ni < 16; ni++) {
                    int c = cbase + ni * 8 + g;
                    uint32_t bf[2];
                    bf[0] = Bs[c * 128 + x0];
                    bf[1] = Bs[c * 128 + x1];
                    mma_f16(acc[ni], af, bf);
                }
            }
        }
        CPWAIT0;
        __syncthreads();

#pragma unroll
        for (int ni2 = 0; ni2 < 4; ni2++) {
            const int mloc = (wid & 1) * 32 + ni2 * 8 + tq * 2;
#pragma unroll
            for (int rs = 0; rs < 2; rs++) {
                const int lr2 = rs ? r1 : r0;
                const float* xr = Xp + lr2 * 260 + mloc;
                float hv[2];
#pragma unroll
                for (int col = 0; col < 2; col++) {
                    int ai = rs * 2 + col;
                    float zi = acc[ni2][ai] + xr[col];
                    float zf = acc[4 + ni2][ai] + xr[64 + col];
                    float zg = acc[8 + ni2][ai] + xr[128 + col];
                    float zo = acc[12 + ni2][ai] + xr[192 + col];
                    int k = ni2 * 4 + ai;
                    float cc = sigf(zf) * creg[k] + sigf(zi) * tanhf(zg);
                    creg[k] = cc;
                    hv[col] = sigf(zo) * tanhf(cc);
                }
                *(uint32_t*)&g_th[(xz + n0 + lr2) * 256 + m0 + mloc] = pack2(hv[0], hv[1]);
            }
        }
        if (t < Ld - 1) gridbar(128, mygen);
    }
}

// ---------------- BN stats over g_th ------------------------------------------
__global__ void k_stats() {
    int m = threadIdx.x;
    long base = (long)blockIdx.x * 65536;
    float s = 0.f, ss = 0.f;
#pragma unroll 4
    for (int n = 0; n < 256; n++) {
        float v = __half2float(g_th[base + (long)n * 256 + m]);
        s += v; ss += v * v;
    }
    atomicAdd(&g_sum[m], (double)s);
    atomicAdd(&g_ssum[m], (double)ss);
}

// ---------------- BN finalize -------------------------------------------------
__global__ void k_finalize(const float* __restrict__ gamma, const float* __restrict__ beta) {
    int m = threadIdx.x;
    double mu = g_sum[m] / 65536.0;
    double var = g_ssum[m] / 65536.0 - mu * mu;
    float q = gamma[m] * (float)(1.0 / sqrt(var + 1e-5));
    g_q[m] = q;
    g_r0[m] = beta[m] - (float)mu * q;
}

// ---------------- launch ------------------------------------------------------
extern "C" void kernel_launch(void* const* d_in, const int* in_sizes, int n_in,
                              void* d_out, int out_size) {
    const float* X     = (const float*)d_in[0];
    const float* dis   = (const float*)d_in[1];
    const float* E1    = (const float*)d_in[2];
    const float* E2    = (const float*)d_in[3];
    const float* W_ih  = (const float*)d_in[4];
    const float* W_hh  = (const float*)d_in[5];
    const float* b_ih  = (const float*)d_in[6];
    const float* b_hh  = (const float*)d_in[7];
    const float* gamma = (const float*)d_in[8];
    const float* beta  = (const float*)d_in[9];
    const float* W_lin = (const float*)d_in[10];
    const float* b_lin = (const float*)d_in[11];
    float* out = (float*)d_out;

    const int GSMEM = 2 * 65536;                                   // 131072 B
    const int LSMEM = (256 * 128 + 64 * 128) * 4 + 64 * 260 * 4;   // 230400 B

    cudaFuncSetAttribute(kh<0, 0, 1>, cudaFuncAttributeMaxDynamicSharedMemorySize, GSMEM);
    cudaFuncSetAttribute(kh<1, 1, 0>, cudaFuncAttributeMaxDynamicSharedMemorySize, GSMEM);
    cudaFuncSetAttribute(kh<0, 1, 1>, cudaFuncAttributeMaxDynamicSharedMemorySize, GSMEM);
    cudaFuncSetAttribute(kh<0, 0, 0>, cudaFuncAttributeMaxDynamicSharedMemorySize, GSMEM);
    cudaFuncSetAttribute(k_lstm, cudaFuncAttributeMaxDynamicSharedMemorySize, LSMEM);

    __half *pXh, *pXwh, *pEch, *pWihh, *pWlinh, *pFch, *pTbh, *pPrh;
    float *pBiasz, *pXproj;
    cudaGetSymbolAddress((void**)&pXh, g_Xh);
    cudaGetSymbolAddress((void**)&pXwh, g_Xwh);
    cudaGetSymbolAddress((void**)&pEch, g_Ech);
    cudaGetSymbolAddress((void**)&pWihh, g_Wihh);
    cudaGetSymbolAddress((void**)&pWlinh, g_Wlinh);
    cudaGetSymbolAddress((void**)&pFch, g_Fch);
    cudaGetSymbolAddress((void**)&pTbh, g_tbh);
    cudaGetSymbolAddress((void**)&pPrh, g_prh);
    cudaGetSymbolAddress((void**)&pBiasz, g_biasz);
    cudaGetSymbolAddress((void**)&pXproj, g_xproj);

    k_init<<<4, 256>>>(b_ih, b_hh);
    k_softmax<<<256, 256>>>(dis);
    k_prep<<<16384, 256>>>((const float4*)X, (const float4*)E1, (const float4*)E2,
                           (const float4*)W_ih, (const float4*)W_hh, (const float4*)W_lin);

    // Fcat
    kh<0, 0, 1><<<dim3(8, 2, 2), 128, GSMEM>>>(
        pWihh, nullptr, 256, 512, pEch, 65536, 256,
        pFch, 256, 512, nullptr, 256);

    // xproj = [Xh | Xwh] @ Fcat^T + biasz (K=512), fp32 out
    kh<1, 1, 0><<<dim3(2, 8, 256), 128, GSMEM>>>(
        pXh, pXwh, 65536, 256, pFch, 0, 512,
        pXproj, 262144, 1024, pBiasz, 512);

    // persistent LSTM (R6 form)
    k_lstm<<<128, 256, LSMEM>>>();

    k_stats<<<256, 256>>>();
    k_finalize<<<1, 256>>>(gamma, beta);
    k_affine<<<32768, 256>>>();

    // proj = tb @ Wlin^T + b_lin (half out)
    kh<0, 1, 1><<<dim3(2, 2, 256), 128, GSMEM>>>(
        pTbh, nullptr, 65536, 256, pWlinh, 0, 256,
        pPrh, 65536, 256, b_lin, 256);

    // out = proj @ tb^T (fp32 out)
    kh<0, 0, 0><<<dim3(2, 2, 256), 128, GSMEM>>>(
        pPrh, nullptr, 65536, 256, pTbh, 65536, 256,
        out, 65536, 256, nullptr, 256);
}

// round 11
// speedup vs baseline: 1.0953x; 1.0945x over previous
#include <cuda_runtime.h>
#include <cuda_fp16.h>
#include <cstdint>
#include <math.h>

#define Bd 8
#define Ld 32
#define HN ((size_t)Bd * Ld * 256 * 256)   // 16777216

// ---------------- device scratch ------------------------------------------
__device__ __align__(16) float g_w[256 * 256];
__device__ __align__(16) __half g_Xh[HN];
__device__ __align__(16) __half g_Xwh[HN];
__device__ __align__(16) __half g_Ech[2 * 256 * 256];
__device__ __align__(16) __half g_Wihh[1024 * 512];
__device__ __align__(16) __half g_Wlinh[256 * 256];
__device__ __align__(16) __half g_Whrh[1024 * 256];
__device__ __align__(16) __half g_Fch[1024 * 512];
__device__ __align__(16) __half g_th[HN];     // LSTM h
__device__ __align__(16) __half g_tbh[HN];    // batchnormed h
__device__ __align__(16) __half g_prh[HN];    // proj
__device__ __align__(16) float g_biasz[1024];
__device__ __align__(16) float g_xproj[HN * 4];
__device__ double g_sum[256], g_ssum[256];
__device__ float g_q[256], g_r0[256];
__device__ unsigned g_barcnt;
__device__ volatile unsigned g_bargen;

// ---------------- helpers --------------------------------------------------
__device__ __forceinline__ uint32_t pack2(float a, float b) {
    __half2 h = __floats2half2_rn(a, b);
    return *(uint32_t*)&h;
}
__device__ __forceinline__ void mma_f16(float* d, const uint32_t* a, const uint32_t* b) {
    asm volatile(
        "mma.sync.aligned.m16n8k16.row.col.f32.f16.f16.f32 "
        "{%0,%1,%2,%3}, {%4,%5,%6,%7}, {%8,%9}, {%0,%1,%2,%3};\n"
        : "+f"(d[0]), "+f"(d[1]), "+f"(d[2]), "+f"(d[3])
        : "r"(a[0]), "r"(a[1]), "r"(a[2]), "r"(a[3]), "r"(b[0]), "r"(b[1]));
}
__device__ __forceinline__ void ldsm4(uint32_t& r0, uint32_t& r1, uint32_t& r2,
                                      uint32_t& r3, uint32_t addr) {
    asm volatile("ldmatrix.sync.aligned.m8n8.x4.shared.b16 {%0,%1,%2,%3}, [%4];"
                 : "=r"(r0), "=r"(r1), "=r"(r2), "=r"(r3) : "r"(addr));
}
__device__ __forceinline__ float sigf(float x) { return 1.f / (1.f + expf(-x)); }

__device__ __forceinline__ void cp16(uint32_t s, const void* g) {
    asm volatile("cp.async.cg.shared.global [%0], [%1], 16;" :: "r"(s), "l"(g));
}
#define CPCOMMIT asm volatile("cp.async.commit_group;")
#define CPWAITG1 asm volatile("cp.async.wait_group 1;")
#define CPWAIT1 asm volatile("cp.async.wait_group 1;")
#define CPWAIT0 asm volatile("cp.async.wait_group 0;")

// ---------------- init ------------------------------------------------------
__global__ void k_init(const float* __restrict__ bih, const float* __restrict__ bhh) {
    int i = blockIdx.x * 256 + threadIdx.x;  // grid 4
    g_biasz[i] = bih[i] + bhh[i];
    if (i < 256) { g_sum[i] = 0.0; g_ssum[i] = 0.0; }
    if (i == 0) { g_barcnt = 0; g_bargen = 0; }
}

// ---------------- softmax of -dis, row-wise ---------------------------------
__global__ void k_softmax(const float* __restrict__ dis) {
    __shared__ float red[256];
    int o = blockIdx.x, t = threadIdx.x;
    float e = expf(-dis[o * 256 + t]);
    red[t] = e;
    __syncthreads();
    for (int s = 128; s > 0; s >>= 1) {
        if (t < s) red[t] += red[t + s];
        __syncthreads();
    }
    g_w[o * 256 + t] = e / red[0];
}

// ---------------- prep: fp16 operand copies ---------------------------------
__global__ void k_prep(const float4* __restrict__ X, const float4* __restrict__ E1,
                       const float4* __restrict__ E2, const float4* __restrict__ W_ih,
                       const float4* __restrict__ W_hh, const float4* __restrict__ W_lin) {
    long i = (long)blockIdx.x * 256 + threadIdx.x;  // grid 16384
    int nd = (int)(i & 16383);
    float4 x = X[i];
    float4 w = ((const float4*)g_w)[nd];
    ((uint2*)g_Xh)[i] = make_uint2(pack2(x.x, x.y), pack2(x.z, x.w));
    ((uint2*)g_Xwh)[i] = make_uint2(pack2(x.x * w.x, x.y * w.y), pack2(x.z * w.z, x.w * w.w));
    if (i < 32768) {
        float4 e = (i < 16384) ? E1[i] : E2[i - 16384];
        ((uint2*)g_Ech)[i] = make_uint2(pack2(e.x, e.y), pack2(e.z, e.w));
    }
    if (i < 131072) {
        float4 v = W_ih[i];
        ((uint2*)g_Wihh)[i] = make_uint2(pack2(v.x, v.y), pack2(v.z, v.w));
    }
    if (i < 65536) {
        float4 v = W_hh[i];
        ((uint2*)g_Whrh)[i] = make_uint2(pack2(v.x, v.y), pack2(v.z, v.w));
    }
    if (i < 16384) {
        float4 v = W_lin[i];
        ((uint2*)g_Wlinh)[i] = make_uint2(pack2(v.x, v.y), pack2(v.z, v.w));
    }
}

// ---------------- tb = half(q*h + r0) ----------------------------------------
__global__ void k_affine() {
    long i = (long)blockIdx.x * 256 + threadIdx.x;  // grid 32768
    uint32_t u = ((const uint32_t*)g_th)[i];
    __half2 h2 = *(__half2*)&u;
    float2 f = __half22float2(h2);
    int c = (int)((i * 2) & 255);
    f.x = f.x * g_q[c] + g_r0[c];
    f.y = f.y * g_q[c + 1] + g_r0[c + 1];
    ((uint32_t*)g_tbh)[i] = pack2(f.x, f.y);
}

// ---------------- 128x128 fp16 GEMM with ldmatrix fragments ------------------
// Smem: per stage A 16KB + B 16KB (stage stride 32KB — 64KB total).
// Store row r sector s at (s ^ (r&7)); ldmatrix reads conflict-free.
template <int AHALF, int HB, int OH>
__global__ void __launch_bounds__(128, 2) kh(
    const __half* __restrict__ A, const __half* __restrict__ A2, long sA, int lda,
    const __half* __restrict__ Bt, long sB, int ldb,
    void* __restrict__ C, long sC, int ldc,
    const float* __restrict__ bias, int K) {
    extern __shared__ uint32_t smu[];
    const uint32_t sbase = (uint32_t)__cvta_generic_to_shared(smu);

    const int tid = threadIdx.x;
    const int z = blockIdx.z;
    const __half* Ab = A + sA * z;
    const __half* Ab2 = AHALF ? (A2 + sA * z) : nullptr;
    const __half* Bb = Bt + sB * z;
    float* Cf = OH ? nullptr : ((float*)C + sC * z);
    __half* Ch = OH ? ((__half*)C + sC * z) : nullptr;
    const int row0 = blockIdx.x * 128, col0 = blockIdx.y * 128;

    const int lane = tid & 31, wid = tid >> 5;
    const int wm = (wid >> 1) * 64, wn = (wid & 1) * 64;
    const int g = lane >> 2, tq = lane & 3;
    const int rL = tid >> 3, sec = tid & 7;
    const int nk = K / 64;

    // ldmatrix lane geometry
    const int g2 = lane >> 3, lr = lane & 7;
    const int aoff = (g2 & 1) * 8 + lr, aksel = g2 >> 1;
    const int boff = (g2 >> 1) * 8 + lr, bksel = g2 & 1;

    auto load = [&](int s, int k0) {
        const __half* Asrc;
        int kc;
        if (AHALF && k0 >= 256) { Asrc = Ab2; kc = k0 - 256 + sec * 8; }
        else { Asrc = Ab; kc = k0 + sec * 8; }
        uint32_t ab = sbase + s * 32768;
        uint32_t bb = ab + 16384;
#pragma unroll
        for (int i = 0; i < 8; i++) {
            int r = rL + i * 16;
            cp16(ab + r * 128 + ((sec ^ (r & 7)) * 16),
                 Asrc + (long)(row0 + r) * lda + kc);
        }
#pragma unroll
        for (int i = 0; i < 8; i++) {
            int r = rL + i * 16;
            cp16(bb + r * 128 + ((sec ^ (r & 7)) * 16),
                 Bb + (long)(col0 + r) * ldb + k0 + sec * 8);
        }
        CPCOMMIT;
    };

    float acc[4][8][4] = {};
    load(0, 0);
    load(1, 64);
    for (int kt = 0; kt < nk; kt++) {
        if (kt + 1 < nk) { CPWAIT1; } else { CPWAIT0; }
        __syncthreads();
        const uint32_t ab = sbase + (kt & 1) * 32768;
        const uint32_t bb = ab + 16384;
#pragma unroll
        for (int kw = 0; kw < 4; kw++) {
            uint32_t af[4][4], bf[8][2];
#pragma unroll
            for (int mi = 0; mi < 4; mi++) {
                int rr = wm + mi * 16 + aoff;
                uint32_t addr = ab + rr * 128 + (((kw * 2 + aksel) ^ lr) * 16);
                ldsm4(af[mi][0], af[mi][1], af[mi][2], af[mi][3], addr);
            }
#pragma unroll
            for (int np = 0; np < 4; np++) {
                int rr = wn + np * 16 + boff;
                uint32_t addr = bb + rr * 128 + (((kw * 2 + bksel) ^ lr) * 16);
                ldsm4(bf[2 * np][0], bf[2 * np][1], bf[2 * np + 1][0], bf[2 * np + 1][1], addr);
            }
#pragma unroll
            for (int mi = 0; mi < 4; mi++)
#pragma unroll
                for (int ni = 0; ni < 8; ni++) mma_f16(acc[mi][ni], af[mi], bf[ni]);
        }
        __syncthreads();
        if (kt + 2 < nk) load(kt & 1, (kt + 2) * 64);
    }
#pragma unroll
    for (int mi = 0; mi < 4; mi++) {
        int rr = row0 + wm + mi * 16 + g;
#pragma unroll
        for (int ni = 0; ni < 8; ni++) {
            int cc = col0 + wn + ni * 8 + tq * 2;
            float b0 = HB ? bias[cc] : 0.f, b1 = HB ? bias[cc + 1] : 0.f;
            float v0 = acc[mi][ni][0] + b0, v1 = acc[mi][ni][1] + b1;
            float v2 = acc[mi][ni][2] + b0, v3 = acc[mi][ni][3] + b1;
            if (OH) {
                *(uint32_t*)&Ch[(long)rr * ldc + cc] = pack2(v0, v1);
                *(uint32_t*)&Ch[(long)(rr + 8) * ldc + cc] = pack2(v2, v3);
            } else {
                Cf[(long)rr * ldc + cc] = v0;
                Cf[(long)rr * ldc + cc + 1] = v1;
                Cf[(long)(rr + 8) * ldc + cc] = v2;
                Cf[(long)(rr + 8) * ldc + cc + 1] = v3;
            }
        }
    }
}

// ---------------- grid barrier ----------------------------------------------
__device__ __forceinline__ void gridbar(unsigned nb, unsigned& mygen) {
    __syncthreads();
    if (threadIdx.x == 0) {
        __threadfence();
        unsigned old = atomicAdd(&g_barcnt, 1u);
        if (old == nb - 1) {
            g_barcnt = 0;
            __threadfence();
            atomicAdd((unsigned*)&g_bargen, 1u);
        } else {
            while (g_bargen <= mygen) {}
        }
        __threadfence();
    }
    __syncthreads();
    mygen++;
}

// ---------------- persistent LSTM (R6 form: resident Whh, smem Xp) -----------
__global__ void __launch_bounds__(256) k_lstm() {
    extern __shared__ uint32_t smL[];
    uint32_t* Bs = smL;                          // 256 x 128 u32 (swizzled)
    uint32_t* As = smL + 256 * 128;              // 64 x 128 u32 (swizzled)
    float* Xp = (float*)(smL + 256 * 128 + 64 * 128);  // 64 x 260 f32

    const int tid = threadIdx.x;
    const int bid = blockIdx.x;
    const int rows0 = (bid >> 2) * 64, m0 = (bid & 3) * 64;
    const int b = rows0 >> 8, n0 = rows0 & 255;
    const int lane = tid & 31, wid = tid >> 5;
    const int g = lane >> 2, tq = lane & 3;
    const int wr = (wid >> 1) * 16;
    const int cbase = (wid & 1) * 128;
    const int r0 = wr + g, r1 = wr + g + 8;

    const uint32_t bsb = (uint32_t)__cvta_generic_to_shared(Bs);
    const uint32_t asb = (uint32_t)__cvta_generic_to_shared(As);
    const uint32_t xpb = (uint32_t)__cvta_generic_to_shared(Xp);

    // ---- preload gathered Whh slice (once) ----
#pragma unroll
    for (int w = 0; w < 32; w++) {
        int idx = tid + w * 256;
        int c = idx >> 5, s = idx & 31;
        int n = c & 127, nw = c >> 7;
        int wrow = (n >> 5) * 256 + m0 + nw * 32 + (n & 31);
        cp16(bsb + (c * 128 + ((s ^ (c & 7)) << 2)) * 4,
             g_Whrh + (long)wrow * 256 + s * 8);
    }
    CPCOMMIT; CPWAIT0;
    __syncthreads();

    float creg[16];
#pragma unroll
    for (int i = 0; i < 16; i++) creg[i] = 0.f;
    unsigned mygen = 0;

    for (int t = 0; t < Ld; t++) {
        const long xz = ((long)b * Ld + t) * 256;

        if (t > 0) {
            const __half* Ab = g_th + (((long)b * Ld + (t - 1)) * 256 + n0) * 256;
#pragma unroll
            for (int w = 0; w < 8; w++) {
                int idx = tid + w * 256;
                int r = idx >> 5, s = idx & 31;
                cp16(asb + (r * 128 + ((s ^ (r & 7)) << 2)) * 4,
                     Ab + (long)r * 256 + s * 8);
            }
        }
        CPCOMMIT;
#pragma unroll
        for (int w = 0; w < 16; w++) {
            int idx = tid + w * 256;
            int r = idx >> 6, s = idx & 63;
            int gate = s >> 4, ms = (s & 15) * 4;
            cp16(xpb + (r * 260 + gate * 64 + ms) * 4,
                 g_xproj + (xz + n0 + r) * 1024 + gate * 256 + m0 + ms);
        }
        CPCOMMIT;
        CPWAITG1;
        __syncthreads();

        float acc[16][4] = {};
        if (t > 0) {
#pragma unroll
            for (int j = 0; j < 16; j++) {
                const int x0 = (((2 * j) ^ g) << 2) + tq;
                const int x1 = (((2 * j + 1) ^ g) << 2) + tq;
                uint32_t af[4];
                af[0] = As[r0 * 128 + x0];
                af[1] = As[r1 * 128 + x0];
                af[2] = As[r0 * 128 + x1];
                af[3] = As[r1 * 128 + x1];
#pragma unroll
                for (int ni = 0; ni < 16; ni++) {
                    int c = cbase + ni * 8 + g;
                    uint32_t bf[2];
                    bf[0] = Bs[c * 128 + x0];
                    bf[1] = Bs[c * 128 + x1];
                    mma_f16(acc[ni], af, bf);
                }
            }
        }
        CPWAIT0;
        __syncthreads();

#pragma unroll
        for (int ni2 = 0; ni2 < 4; ni2++) {
            const int mloc = (wid & 1) * 32 + ni2 * 8 + tq * 2;
#pragma unroll
            for (int rs = 0; rs < 2; rs++) {
                const int lr2 = rs ? r1 : r0;
                const float* xr = Xp + lr2 * 260 + mloc;
                float hv[2];
#pragma unroll
                for (int col = 0; col < 2; col++) {
                    int ai = rs * 2 + col;
                    float zi = acc[ni2][ai] + xr[col];
                    float zf = acc[4 + ni2][ai] + xr[64 + col];
                    float zg = acc[8 + ni2][ai] + xr[128 + col];
                    float zo = acc[12 + ni2][ai] + xr[192 + col];
                    int k = ni2 * 4 + ai;
                    float cc = sigf(zf) * creg[k] + sigf(zi) * tanhf(zg);
                    creg[k] = cc;
                    hv[col] = sigf(zo) * tanhf(cc);
                }
                *(uint32_t*)&g_th[(xz + n0 + lr2) * 256 + m0 + mloc] = pack2(hv[0], hv[1]);
            }
        }
        if (t < Ld - 1) gridbar(128, mygen);
    }
}

// ---------------- BN stats over g_th ------------------------------------------
__global__ void k_stats() {
    int m = threadIdx.x;
    long base = (long)blockIdx.x * 65536;
    float s = 0.f, ss = 0.f;
#pragma unroll 4
    for (int n = 0; n < 256; n++) {
        float v = __half2float(g_th[base + (long)n * 256 + m]);
        s += v; ss += v * v;
    }
    atomicAdd(&g_sum[m], (double)s);
    atomicAdd(&g_ssum[m], (double)ss);
}

// ---------------- BN finalize -------------------------------------------------
__global__ void k_finalize(const float* __restrict__ gamma, const float* __restrict__ beta) {
    int m = threadIdx.x;
    double mu = g_sum[m] / 65536.0;
    double var = g_ssum[m] / 65536.0 - mu * mu;
    float q = gamma[m] * (float)(1.0 / sqrt(var + 1e-5));
    g_q[m] = q;
    g_r0[m] = beta[m] - (float)mu * q;
}

// ---------------- launch ------------------------------------------------------
extern "C" void kernel_launch(void* const* d_in, const int* in_sizes, int n_in,
                              void* d_out, int out_size) {
    const float* X     = (const float*)d_in[0];
    const float* dis   = (const float*)d_in[1];
    const float* E1    = (const float*)d_in[2];
    const float* E2    = (const float*)d_in[3];
    const float* W_ih  = (const float*)d_in[4];
    const float* W_hh  = (const float*)d_in[5];
    const float* b_ih  = (const float*)d_in[6];
    const float* b_hh  = (const float*)d_in[7];
    const float* gamma = (const float*)d_in[8];
    const float* beta  = (const float*)d_in[9];
    const float* W_lin = (const float*)d_in[10];
    const float* b_lin = (const float*)d_in[11];
    float* out = (float*)d_out;

    const int GSMEM = 2 * 32768;                                   // 65536 B
    const int LSMEM = (256 * 128 + 64 * 128) * 4 + 64 * 260 * 4;   // 230400 B

    cudaFuncSetAttribute(kh<0, 0, 1>, cudaFuncAttributeMaxDynamicSharedMemorySize, GSMEM);
    cudaFuncSetAttribute(kh<1, 1, 0>, cudaFuncAttributeMaxDynamicSharedMemorySize, GSMEM);
    cudaFuncSetAttribute(kh<0, 1, 1>, cudaFuncAttributeMaxDynamicSharedMemorySize, GSMEM);
    cudaFuncSetAttribute(kh<0, 0, 0>, cudaFuncAttributeMaxDynamicSharedMemorySize, GSMEM);
    cudaFuncSetAttribute(k_lstm, cudaFuncAttributeMaxDynamicSharedMemorySize, LSMEM);

    __half *pXh, *pXwh, *pEch, *pWihh, *pWlinh, *pFch, *pTbh, *pPrh;
    float *pBiasz, *pXproj;
    cudaGetSymbolAddress((void**)&pXh, g_Xh);
    cudaGetSymbolAddress((void**)&pXwh, g_Xwh);
    cudaGetSymbolAddress((void**)&pEch, g_Ech);
    cudaGetSymbolAddress((void**)&pWihh, g_Wihh);
    cudaGetSymbolAddress((void**)&pWlinh, g_Wlinh);
    cudaGetSymbolAddress((void**)&pFch, g_Fch);
    cudaGetSymbolAddress((void**)&pTbh, g_tbh);
    cudaGetSymbolAddress((void**)&pPrh, g_prh);
    cudaGetSymbolAddress((void**)&pBiasz, g_biasz);
    cudaGetSymbolAddress((void**)&pXproj, g_xproj);

    k_init<<<4, 256>>>(b_ih, b_hh);
    k_softmax<<<256, 256>>>(dis);
    k_prep<<<16384, 256>>>((const float4*)X, (const float4*)E1, (const float4*)E2,
                           (const float4*)W_ih, (const float4*)W_hh, (const float4*)W_lin);

    // Fcat
    kh<0, 0, 1><<<dim3(8, 2, 2), 128, GSMEM>>>(
        pWihh, nullptr, 256, 512, pEch, 65536, 256,
        pFch, 256, 512, nullptr, 256);

    // xproj = [Xh | Xwh] @ Fcat^T + biasz (K=512), fp32 out
    kh<1, 1, 0><<<dim3(2, 8, 256), 128, GSMEM>>>(
        pXh, pXwh, 65536, 256, pFch, 0, 512,
        pXproj, 262144, 1024, pBiasz, 512);

    // persistent LSTM (R6 form)
    k_lstm<<<128, 256, LSMEM>>>();

    k_stats<<<256, 256>>>();
    k_finalize<<<1, 256>>>(gamma, beta);
    k_affine<<<32768, 256>>>();

    // proj = tb @ Wlin^T + b_lin (half out)
    kh<0, 1, 1><<<dim3(2, 2, 256), 128, GSMEM>>>(
        pTbh, nullptr, 65536, 256, pWlinh, 0, 256,
        pPrh, 65536, 256, b_lin, 256);

    // out = proj @ tb^T (fp32 out)
    kh<0, 0, 0><<<dim3(2, 2, 256), 128, GSMEM>>>(
        pPrh, nullptr, 65536, 256, pTbh, 65536, 256,
        out, 65536, 256, nullptr, 256);
}

// round 12
// speedup vs baseline: 1.1052x; 1.0090x over previous
#include <cuda_runtime.h>
#include <cuda_fp16.h>
#include <cstdint>
#include <math.h>

#define Bd 8
#define Ld 32
#define HN ((size_t)Bd * Ld * 256 * 256)   // 16777216

// ---------------- device scratch ------------------------------------------
__device__ __align__(16) float g_w[256 * 256];
__device__ __align__(16) __half g_Xh[HN];
__device__ __align__(16) __half g_Xwh[HN];
__device__ __align__(16) __half g_Ech[2 * 256 * 256];
__device__ __align__(16) __half g_Wihh[1024 * 512];
__device__ __align__(16) __half g_Wlinh[256 * 256];
__device__ __align__(16) __half g_Whrh[1024 * 256];
__device__ __align__(16) __half g_Fch[1024 * 512];
__device__ __align__(16) __half g_th[HN];     // LSTM h
__device__ __align__(16) __half g_tbh[HN];    // batchnormed h
__device__ __align__(16) __half g_prh[HN];    // proj
__device__ __align__(16) float g_biasz[1024];
__device__ __align__(16) float g_xproj[HN * 4];
__device__ double g_sum[256], g_ssum[256];
__device__ float g_q[256], g_r0[256];
__device__ unsigned g_barcnt;
__device__ volatile unsigned g_bargen;

// ---------------- helpers --------------------------------------------------
__device__ __forceinline__ uint32_t pack2(float a, float b) {
    __half2 h = __floats2half2_rn(a, b);
    return *(uint32_t*)&h;
}
__device__ __forceinline__ void mma_f16(float* d, const uint32_t* a, const uint32_t* b) {
    asm volatile(
        "mma.sync.aligned.m16n8k16.row.col.f32.f16.f16.f32 "
        "{%0,%1,%2,%3}, {%4,%5,%6,%7}, {%8,%9}, {%0,%1,%2,%3};\n"
        : "+f"(d[0]), "+f"(d[1]), "+f"(d[2]), "+f"(d[3])
        : "r"(a[0]), "r"(a[1]), "r"(a[2]), "r"(a[3]), "r"(b[0]), "r"(b[1]));
}
__device__ __forceinline__ void ldsm4(uint32_t& r0, uint32_t& r1, uint32_t& r2,
                                      uint32_t& r3, uint32_t addr) {
    asm volatile("ldmatrix.sync.aligned.m8n8.x4.shared.b16 {%0,%1,%2,%3}, [%4];"
                 : "=r"(r0), "=r"(r1), "=r"(r2), "=r"(r3) : "r"(addr));
}
__device__ __forceinline__ float sigf(float x) { return 1.f / (1.f + expf(-x)); }

__device__ __forceinline__ void cp16(uint32_t s, const void* g) {
    asm volatile("cp.async.cg.shared.global [%0], [%1], 16;" :: "r"(s), "l"(g));
}
#define CPCOMMIT asm volatile("cp.async.commit_group;")
#define CPWAITG1 asm volatile("cp.async.wait_group 1;")
#define CPWAIT1 asm volatile("cp.async.wait_group 1;")
#define CPWAIT0 asm volatile("cp.async.wait_group 0;")

// ---------------- init ------------------------------------------------------
__global__ void k_init(const float* __restrict__ bih, const float* __restrict__ bhh) {
    int i = blockIdx.x * 256 + threadIdx.x;  // grid 4
    g_biasz[i] = bih[i] + bhh[i];
    if (i < 256) { g_sum[i] = 0.0; g_ssum[i] = 0.0; }
    if (i == 0) { g_barcnt = 0; g_bargen = 0; }
}

// ---------------- softmax of -dis, row-wise ---------------------------------
__global__ void k_softmax(const float* __restrict__ dis) {
    __shared__ float red[256];
    int o = blockIdx.x, t = threadIdx.x;
    float e = expf(-dis[o * 256 + t]);
    red[t] = e;
    __syncthreads();
    for (int s = 128; s > 0; s >>= 1) {
        if (t < s) red[t] += red[t + s];
        __syncthreads();
    }
    g_w[o * 256 + t] = e / red[0];
}

// ---------------- prep: fp16 operand copies ---------------------------------
__global__ void k_prep(const float4* __restrict__ X, const float4* __restrict__ E1,
                       const float4* __restrict__ E2, const float4* __restrict__ W_ih,
                       const float4* __restrict__ W_hh, const float4* __restrict__ W_lin) {
    long i = (long)blockIdx.x * 256 + threadIdx.x;  // grid 16384
    int nd = (int)(i & 16383);
    float4 x = X[i];
    float4 w = ((const float4*)g_w)[nd];
    ((uint2*)g_Xh)[i] = make_uint2(pack2(x.x, x.y), pack2(x.z, x.w));
    ((uint2*)g_Xwh)[i] = make_uint2(pack2(x.x * w.x, x.y * w.y), pack2(x.z * w.z, x.w * w.w));
    if (i < 32768) {
        float4 e = (i < 16384) ? E1[i] : E2[i - 16384];
        ((uint2*)g_Ech)[i] = make_uint2(pack2(e.x, e.y), pack2(e.z, e.w));
    }
    if (i < 131072) {
        float4 v = W_ih[i];
        ((uint2*)g_Wihh)[i] = make_uint2(pack2(v.x, v.y), pack2(v.z, v.w));
    }
    if (i < 65536) {
        float4 v = W_hh[i];
        ((uint2*)g_Whrh)[i] = make_uint2(pack2(v.x, v.y), pack2(v.z, v.w));
    }
    if (i < 16384) {
        float4 v = W_lin[i];
        ((uint2*)g_Wlinh)[i] = make_uint2(pack2(v.x, v.y), pack2(v.z, v.w));
    }
}

// ---------------- tb = half(q*h + r0) ----------------------------------------
__global__ void k_affine() {
    long i = (long)blockIdx.x * 256 + threadIdx.x;  // grid 32768
    uint32_t u = ((const uint32_t*)g_th)[i];
    __half2 h2 = *(__half2*)&u;
    float2 f = __half22float2(h2);
    int c = (int)((i * 2) & 255);
    f.x = f.x * g_q[c] + g_r0[c];
    f.y = f.y * g_q[c + 1] + g_r0[c + 1];
    ((uint32_t*)g_tbh)[i] = pack2(f.x, f.y);
}

// ---------------- 128x128 fp16 GEMM with ldmatrix fragments ------------------
// Smem: per stage A 16KB + B 16KB (stage stride 32KB — 64KB total).
// Store row r sector s at (s ^ (r&7)); ldmatrix reads conflict-free.
template <int AHALF, int HB, int OH>
__global__ void __launch_bounds__(128, 2) kh(
    const __half* __restrict__ A, const __half* __restrict__ A2, long sA, int lda,
    const __half* __restrict__ Bt, long sB, int ldb,
    void* __restrict__ C, long sC, int ldc,
    const float* __restrict__ bias, int K) {
    extern __shared__ uint32_t smu[];
    const uint32_t sbase = (uint32_t)__cvta_generic_to_shared(smu);

    const int tid = threadIdx.x;
    const int z = blockIdx.z;
    const __half* Ab = A + sA * z;
    const __half* Ab2 = AHALF ? (A2 + sA * z) : nullptr;
    const __half* Bb = Bt + sB * z;
    float* Cf = OH ? nullptr : ((float*)C + sC * z);
    __half* Ch = OH ? ((__half*)C + sC * z) : nullptr;
    const int row0 = blockIdx.x * 128, col0 = blockIdx.y * 128;

    const int lane = tid & 31, wid = tid >> 5;
    const int wm = (wid >> 1) * 64, wn = (wid & 1) * 64;
    const int g = lane >> 2, tq = lane & 3;
    const int rL = tid >> 3, sec = tid & 7;
    const int nk = K / 64;

    // ldmatrix lane geometry
    const int g2 = lane >> 3, lr = lane & 7;
    const int aoff = (g2 & 1) * 8 + lr, aksel = g2 >> 1;
    const int boff = (g2 >> 1) * 8 + lr, bksel = g2 & 1;

    auto load = [&](int s, int k0) {
        const __half* Asrc;
        int kc;
        if (AHALF && k0 >= 256) { Asrc = Ab2; kc = k0 - 256 + sec * 8; }
        else { Asrc = Ab; kc = k0 + sec * 8; }
        uint32_t ab = sbase + s * 32768;
        uint32_t bb = ab + 16384;
#pragma unroll
        for (int i = 0; i < 8; i++) {
            int r = rL + i * 16;
            cp16(ab + r * 128 + ((sec ^ (r & 7)) * 16),
                 Asrc + (long)(row0 + r) * lda + kc);
        }
#pragma unroll
        for (int i = 0; i < 8; i++) {
            int r = rL + i * 16;
            cp16(bb + r * 128 + ((sec ^ (r & 7)) * 16),
                 Bb + (long)(col0 + r) * ldb + k0 + sec * 8);
        }
        CPCOMMIT;
    };

    float acc[4][8][4] = {};
    load(0, 0);
    load(1, 64);
    for (int kt = 0; kt < nk; kt++) {
        if (kt + 1 < nk) { CPWAIT1; } else { CPWAIT0; }
        __syncthreads();
        const uint32_t ab = sbase + (kt & 1) * 32768;
        const uint32_t bb = ab + 16384;
#pragma unroll
        for (int kw = 0; kw < 4; kw++) {
            uint32_t af[4][4], bf[8][2];
#pragma unroll
            for (int mi = 0; mi < 4; mi++) {
                int rr = wm + mi * 16 + aoff;
                uint32_t addr = ab + rr * 128 + (((kw * 2 + aksel) ^ lr) * 16);
                ldsm4(af[mi][0], af[mi][1], af[mi][2], af[mi][3], addr);
            }
#pragma unroll
            for (int np = 0; np < 4; np++) {
                int rr = wn + np * 16 + boff;
                uint32_t addr = bb + rr * 128 + (((kw * 2 + bksel) ^ lr) * 16);
                ldsm4(bf[2 * np][0], bf[2 * np][1], bf[2 * np + 1][0], bf[2 * np + 1][1], addr);
            }
#pragma unroll
            for (int mi = 0; mi < 4; mi++)
#pragma unroll
                for (int ni = 0; ni < 8; ni++) mma_f16(acc[mi][ni], af[mi], bf[ni]);
        }
        __syncthreads();
        if (kt + 2 < nk) load(kt & 1, (kt + 2) * 64);
    }
#pragma unroll
    for (int mi = 0; mi < 4; mi++) {
        int rr = row0 + wm + mi * 16 + g;
#pragma unroll
        for (int ni = 0; ni < 8; ni++) {
            int cc = col0 + wn + ni * 8 + tq * 2;
            float b0 = HB ? bias[cc] : 0.f, b1 = HB ? bias[cc + 1] : 0.f;
            float v0 = acc[mi][ni][0] + b0, v1 = acc[mi][ni][1] + b1;
            float v2 = acc[mi][ni][2] + b0, v3 = acc[mi][ni][3] + b1;
            if (OH) {
                *(uint32_t*)&Ch[(long)rr * ldc + cc] = pack2(v0, v1);
                *(uint32_t*)&Ch[(long)(rr + 8) * ldc + cc] = pack2(v2, v3);
            } else {
                Cf[(long)rr * ldc + cc] = v0;
                Cf[(long)rr * ldc + cc + 1] = v1;
                Cf[(long)(rr + 8) * ldc + cc] = v2;
                Cf[(long)(rr + 8) * ldc + cc + 1] = v3;
            }
        }
    }
}

// ---------------- grid barrier ----------------------------------------------
__device__ __forceinline__ void gridbar(unsigned nb, unsigned& mygen) {
    __syncthreads();
    if (threadIdx.x == 0) {
        __threadfence();
        unsigned old = atomicAdd(&g_barcnt, 1u);
        if (old == nb - 1) {
            g_barcnt = 0;
            __threadfence();
            atomicAdd((unsigned*)&g_bargen, 1u);
        } else {
            while (g_bargen <= mygen) {}
        }
        __threadfence();
    }
    __syncthreads();
    mygen++;
}

// ---------------- persistent LSTM: resident Whh, ldmatrix fragments ----------
// As/Bs rows are 512B (full K), 16B sectors stored at (s ^ (row&7))*16 — the
// same swizzle the GEMM kernel uses, so ldmatrix geometry transfers directly.
__global__ void __launch_bounds__(256) k_lstm() {
    extern __shared__ uint32_t smL[];
    uint32_t* Bs = smL;                          // 256 x 128 u32 (swizzled)
    uint32_t* As = smL + 256 * 128;              // 64 x 128 u32 (swizzled)
    float* Xp = (float*)(smL + 256 * 128 + 64 * 128);  // 64 x 260 f32

    const int tid = threadIdx.x;
    const int bid = blockIdx.x;
    const int rows0 = (bid >> 2) * 64, m0 = (bid & 3) * 64;
    const int b = rows0 >> 8, n0 = rows0 & 255;
    const int lane = tid & 31, wid = tid >> 5;
    const int g = lane >> 2, tq = lane & 3;
    const int wr = (wid >> 1) * 16;
    const int cbase = (wid & 1) * 128;
    const int r0 = wr + g, r1 = wr + g + 8;

    // ldmatrix lane geometry (same as GEMM kernel)
    const int g2 = lane >> 3, lr = lane & 7;
    const int aoff = (g2 & 1) * 8 + lr, aksel = g2 >> 1;
    const int boff = (g2 >> 1) * 8 + lr, bksel = g2 & 1;

    const uint32_t bsb = (uint32_t)__cvta_generic_to_shared(Bs);
    const uint32_t asb = (uint32_t)__cvta_generic_to_shared(As);
    const uint32_t xpb = (uint32_t)__cvta_generic_to_shared(Xp);

    // ---- preload gathered Whh slice (once) ----
#pragma unroll
    for (int w = 0; w < 32; w++) {
        int idx = tid + w * 256;
        int c = idx >> 5, s = idx & 31;
        int n = c & 127, nw = c >> 7;
        int wrow = (n >> 5) * 256 + m0 + nw * 32 + (n & 31);
        cp16(bsb + (c * 128 + ((s ^ (c & 7)) << 2)) * 4,
             g_Whrh + (long)wrow * 256 + s * 8);
    }
    CPCOMMIT; CPWAIT0;
    __syncthreads();

    float creg[16];
#pragma unroll
    for (int i = 0; i < 16; i++) creg[i] = 0.f;
    unsigned mygen = 0;

    // precompute per-lane A fragment row (constant across steps/j)
    const int arow = wr + aoff;
    const uint32_t abase = asb + arow * 512;
    const int amask = arow & 7;

    for (int t = 0; t < Ld; t++) {
        const long xz = ((long)b * Ld + t) * 256;

        if (t > 0) {
            const __half* Ab = g_th + (((long)b * Ld + (t - 1)) * 256 + n0) * 256;
#pragma unroll
            for (int w = 0; w < 8; w++) {
                int idx = tid + w * 256;
                int r = idx >> 5, s = idx & 31;
                cp16(asb + (r * 128 + ((s ^ (r & 7)) << 2)) * 4,
                     Ab + (long)r * 256 + s * 8);
            }
        }
        CPCOMMIT;
#pragma unroll
        for (int w = 0; w < 16; w++) {
            int idx = tid + w * 256;
            int r = idx >> 6, s = idx & 63;
            int gate = s >> 4, ms = (s & 15) * 4;
            cp16(xpb + (r * 260 + gate * 64 + ms) * 4,
                 g_xproj + (xz + n0 + r) * 1024 + gate * 256 + m0 + ms);
        }
        CPCOMMIT;
        CPWAITG1;
        __syncthreads();

        float acc[16][4] = {};
        if (t > 0) {
#pragma unroll
            for (int j = 0; j < 16; j++) {
                uint32_t af[4];
                ldsm4(af[0], af[1], af[2], af[3],
                      abase + (((j * 2 + aksel) ^ amask) * 16));
#pragma unroll
                for (int np = 0; np < 8; np++) {
                    int col = cbase + np * 16 + boff;
                    uint32_t bf0[2], bf1[2];
                    ldsm4(bf0[0], bf0[1], bf1[0], bf1[1],
                          bsb + col * 512 + (((j * 2 + bksel) ^ (col & 7)) * 16));
                    mma_f16(acc[2 * np], af, bf0);
                    mma_f16(acc[2 * np + 1], af, bf1);
                }
            }
        }
        CPWAIT0;
        __syncthreads();

#pragma unroll
        for (int ni2 = 0; ni2 < 4; ni2++) {
            const int mloc = (wid & 1) * 32 + ni2 * 8 + tq * 2;
#pragma unroll
            for (int rs = 0; rs < 2; rs++) {
                const int lr2 = rs ? r1 : r0;
                const float* xr = Xp + lr2 * 260 + mloc;
                float hv[2];
#pragma unroll
                for (int col = 0; col < 2; col++) {
                    int ai = rs * 2 + col;
                    float zi = acc[ni2][ai] + xr[col];
                    float zf = acc[4 + ni2][ai] + xr[64 + col];
                    float zg = acc[8 + ni2][ai] + xr[128 + col];
                    float zo = acc[12 + ni2][ai] + xr[192 + col];
                    int k = ni2 * 4 + ai;
                    float cc = sigf(zf) * creg[k] + sigf(zi) * tanhf(zg);
                    creg[k] = cc;
                    hv[col] = sigf(zo) * tanhf(cc);
                }
                *(uint32_t*)&g_th[(xz + n0 + lr2) * 256 + m0 + mloc] = pack2(hv[0], hv[1]);
            }
        }
        if (t < Ld - 1) gridbar(128, mygen);
    }
}

// ---------------- BN stats over g_th ------------------------------------------
__global__ void k_stats() {
    int m = threadIdx.x;
    long base = (long)blockIdx.x * 65536;
    float s = 0.f, ss = 0.f;
#pragma unroll 4
    for (int n = 0; n < 256; n++) {
        float v = __half2float(g_th[base + (long)n * 256 + m]);
        s += v; ss += v * v;
    }
    atomicAdd(&g_sum[m], (double)s);
    atomicAdd(&g_ssum[m], (double)ss);
}

// ---------------- BN finalize -------------------------------------------------
__global__ void k_finalize(const float* __restrict__ gamma, const float* __restrict__ beta) {
    int m = threadIdx.x;
    double mu = g_sum[m] / 65536.0;
    double var = g_ssum[m] / 65536.0 - mu * mu;
    float q = gamma[m] * (float)(1.0 / sqrt(var + 1e-5));
    g_q[m] = q;
    g_r0[m] = beta[m] - (float)mu * q;
}

// ---------------- launch ------------------------------------------------------
extern "C" void kernel_launch(void* const* d_in, const int* in_sizes, int n_in,
                              void* d_out, int out_size) {
    const float* X     = (const float*)d_in[0];
    const float* dis   = (const float*)d_in[1];
    const float* E1    = (const float*)d_in[2];
    const float* E2    = (const float*)d_in[3];
    const float* W_ih  = (const float*)d_in[4];
    const float* W_hh  = (const float*)d_in[5];
    const float* b_ih  = (const float*)d_in[6];
    const float* b_hh  = (const float*)d_in[7];
    const float* gamma = (const float*)d_in[8];
    const float* beta  = (const float*)d_in[9];
    const float* W_lin = (const float*)d_in[10];
    const float* b_lin = (const float*)d_in[11];
    float* out = (float*)d_out;

    const int GSMEM = 2 * 32768;                                   // 65536 B
    const int LSMEM = (256 * 128 + 64 * 128) * 4 + 64 * 260 * 4;   // 230400 B

    cudaFuncSetAttribute(kh<0, 0, 1>, cudaFuncAttributeMaxDynamicSharedMemorySize, GSMEM);
    cudaFuncSetAttribute(kh<1, 1, 0>, cudaFuncAttributeMaxDynamicSharedMemorySize, GSMEM);
    cudaFuncSetAttribute(kh<0, 1, 1>, cudaFuncAttributeMaxDynamicSharedMemorySize, GSMEM);
    cudaFuncSetAttribute(kh<0, 0, 0>, cudaFuncAttributeMaxDynamicSharedMemorySize, GSMEM);
    cudaFuncSetAttribute(k_lstm, cudaFuncAttributeMaxDynamicSharedMemorySize, LSMEM);

    __half *pXh, *pXwh, *pEch, *pWihh, *pWlinh, *pFch, *pTbh, *pPrh;
    float *pBiasz, *pXproj;
    cudaGetSymbolAddress((void**)&pXh, g_Xh);
    cudaGetSymbolAddress((void**)&pXwh, g_Xwh);
    cudaGetSymbolAddress((void**)&pEch, g_Ech);
    cudaGetSymbolAddress((void**)&pWihh, g_Wihh);
    cudaGetSymbolAddress((void**)&pWlinh, g_Wlinh);
    cudaGetSymbolAddress((void**)&pFch, g_Fch);
    cudaGetSymbolAddress((void**)&pTbh, g_tbh);
    cudaGetSymbolAddress((void**)&pPrh, g_prh);
    cudaGetSymbolAddress((void**)&pBiasz, g_biasz);
    cudaGetSymbolAddress((void**)&pXproj, g_xproj);

    k_init<<<4, 256>>>(b_ih, b_hh);
    k_softmax<<<256, 256>>>(dis);
    k_prep<<<16384, 256>>>((const float4*)X, (const float4*)E1, (const float4*)E2,
                           (const float4*)W_ih, (const float4*)W_hh, (const float4*)W_lin);

    // Fcat
    kh<0, 0, 1><<<dim3(8, 2, 2), 128, GSMEM>>>(
        pWihh, nullptr, 256, 512, pEch, 65536, 256,
        pFch, 256, 512, nullptr, 256);

    // xproj = [Xh | Xwh] @ Fcat^T + biasz (K=512), fp32 out
    kh<1, 1, 0><<<dim3(2, 8, 256), 128, GSMEM>>>(
        pXh, pXwh, 65536, 256, pFch, 0, 512,
        pXproj, 262144, 1024, pBiasz, 512);

    // persistent LSTM (ldmatrix fragments)
    k_lstm<<<128, 256, LSMEM>>>();

    k_stats<<<256, 256>>>();
    k_finalize<<<1, 256>>>(gamma, beta);
    k_affine<<<32768, 256>>>();

    // proj = tb @ Wlin^T + b_lin (half out)
    kh<0, 1, 1><<<dim3(2, 2, 256), 128, GSMEM>>>(
        pTbh, nullptr, 65536, 256, pWlinh, 0, 256,
        pPrh, 65536, 256, b_lin, 256);

    // out = proj @ tb^T (fp32 out)
    kh<0, 0, 0><<<dim3(2, 2, 256), 128, GSMEM>>>(
        pPrh, nullptr, 65536, 256, pTbh, 65536, 256,
        out, 65536, 256, nullptr, 256);
}

// round 13
// speedup vs baseline: 1.2081x; 1.0931x over previous
#include <cuda_runtime.h>
#include <cuda_fp16.h>
#include <cstdint>
#include <math.h>

#define Bd 8
#define Ld 32
#define HN ((size_t)Bd * Ld * 256 * 256)   // 16777216

// ---------------- device scratch ------------------------------------------
__device__ __align__(16) float g_w[256 * 256];
__device__ __align__(16) __half g_Xh[HN];
__device__ __align__(16) __half g_Xwh[HN];
__device__ __align__(16) __half g_Ech[2 * 256 * 256];
__device__ __align__(16) __half g_Wihh[1024 * 512];
__device__ __align__(16) __half g_Wlinh[256 * 256];
__device__ __align__(16) __half g_Whrh[1024 * 256];
__device__ __align__(16) __half g_Fch[1024 * 512];
__device__ __align__(16) __half g_th[HN];      // LSTM h
__device__ __align__(16) __half g_tbh[HN];     // batchnormed h
__device__ __align__(16) __half g_prh[HN];     // proj
__device__ __align__(16) __half g_xpjh[HN * 4];// xproj (fp16)
__device__ __align__(16) float g_biasz[1024];
__device__ double g_sum[256], g_ssum[256];
__device__ float g_q[256], g_r0[256];
__device__ unsigned g_barcnt;
__device__ volatile unsigned g_bargen;

// ---------------- helpers --------------------------------------------------
__device__ __forceinline__ uint32_t pack2(float a, float b) {
    __half2 h = __floats2half2_rn(a, b);
    return *(uint32_t*)&h;
}
__device__ __forceinline__ void mma_f16(float* d, const uint32_t* a, const uint32_t* b) {
    asm volatile(
        "mma.sync.aligned.m16n8k16.row.col.f32.f16.f16.f32 "
        "{%0,%1,%2,%3}, {%4,%5,%6,%7}, {%8,%9}, {%0,%1,%2,%3};\n"
        : "+f"(d[0]), "+f"(d[1]), "+f"(d[2]), "+f"(d[3])
        : "r"(a[0]), "r"(a[1]), "r"(a[2]), "r"(a[3]), "r"(b[0]), "r"(b[1]));
}
__device__ __forceinline__ void ldsm4(uint32_t& r0, uint32_t& r1, uint32_t& r2,
                                      uint32_t& r3, uint32_t addr) {
    asm volatile("ldmatrix.sync.aligned.m8n8.x4.shared.b16 {%0,%1,%2,%3}, [%4];"
                 : "=r"(r0), "=r"(r1), "=r"(r2), "=r"(r3) : "r"(addr));
}
__device__ __forceinline__ float sigf(float x) { return 1.f / (1.f + expf(-x)); }

__device__ __forceinline__ void cp16(uint32_t s, const void* g) {
    asm volatile("cp.async.cg.shared.global [%0], [%1], 16;" :: "r"(s), "l"(g));
}
#define CPCOMMIT asm volatile("cp.async.commit_group;")
#define CPWAITG1 asm volatile("cp.async.wait_group 1;")
#define CPWAIT1 asm volatile("cp.async.wait_group 1;")
#define CPWAIT0 asm volatile("cp.async.wait_group 0;")

// ---------------- init ------------------------------------------------------
__global__ void k_init(const float* __restrict__ bih, const float* __restrict__ bhh) {
    int i = blockIdx.x * 256 + threadIdx.x;  // grid 4
    g_biasz[i] = bih[i] + bhh[i];
    if (i < 256) { g_sum[i] = 0.0; g_ssum[i] = 0.0; }
    if (i == 0) { g_barcnt = 0; g_bargen = 0; }
}

// ---------------- softmax of -dis, row-wise ---------------------------------
__global__ void k_softmax(const float* __restrict__ dis) {
    __shared__ float red[256];
    int o = blockIdx.x, t = threadIdx.x;
    float e = expf(-dis[o * 256 + t]);
    red[t] = e;
    __syncthreads();
    for (int s = 128; s > 0; s >>= 1) {
        if (t < s) red[t] += red[t + s];
        __syncthreads();
    }
    g_w[o * 256 + t] = e / red[0];
}

// ---------------- prep: fp16 operand copies ---------------------------------
__global__ void k_prep(const float4* __restrict__ X, const float4* __restrict__ E1,
                       const float4* __restrict__ E2, const float4* __restrict__ W_ih,
                       const float4* __restrict__ W_hh, const float4* __restrict__ W_lin) {
    long i = (long)blockIdx.x * 256 + threadIdx.x;  // grid 16384
    int nd = (int)(i & 16383);
    float4 x = X[i];
    float4 w = ((const float4*)g_w)[nd];
    ((uint2*)g_Xh)[i] = make_uint2(pack2(x.x, x.y), pack2(x.z, x.w));
    ((uint2*)g_Xwh)[i] = make_uint2(pack2(x.x * w.x, x.y * w.y), pack2(x.z * w.z, x.w * w.w));
    if (i < 32768) {
        float4 e = (i < 16384) ? E1[i] : E2[i - 16384];
        ((uint2*)g_Ech)[i] = make_uint2(pack2(e.x, e.y), pack2(e.z, e.w));
    }
    if (i < 131072) {
        float4 v = W_ih[i];
        ((uint2*)g_Wihh)[i] = make_uint2(pack2(v.x, v.y), pack2(v.z, v.w));
    }
    if (i < 65536) {
        float4 v = W_hh[i];
        ((uint2*)g_Whrh)[i] = make_uint2(pack2(v.x, v.y), pack2(v.z, v.w));
    }
    if (i < 16384) {
        float4 v = W_lin[i];
        ((uint2*)g_Wlinh)[i] = make_uint2(pack2(v.x, v.y), pack2(v.z, v.w));
    }
}

// ---------------- tb = half(q*h + r0) ----------------------------------------
__global__ void k_affine() {
    long i = (long)blockIdx.x * 256 + threadIdx.x;  // grid 32768
    uint32_t u = ((const uint32_t*)g_th)[i];
    __half2 h2 = *(__half2*)&u;
    float2 f = __half22float2(h2);
    int c = (int)((i * 2) & 255);
    f.x = f.x * g_q[c] + g_r0[c];
    f.y = f.y * g_q[c + 1] + g_r0[c + 1];
    ((uint32_t*)g_tbh)[i] = pack2(f.x, f.y);
}

// ---------------- 128x128 fp16 GEMM with ldmatrix fragments ------------------
template <int AHALF, int HB, int OH>
__global__ void __launch_bounds__(128, 2) kh(
    const __half* __restrict__ A, const __half* __restrict__ A2, long sA, int lda,
    const __half* __restrict__ Bt, long sB, int ldb,
    void* __restrict__ C, long sC, int ldc,
    const float* __restrict__ bias, int K) {
    extern __shared__ uint32_t smu[];
    const uint32_t sbase = (uint32_t)__cvta_generic_to_shared(smu);

    const int tid = threadIdx.x;
    const int z = blockIdx.z;
    const __half* Ab = A + sA * z;
    const __half* Ab2 = AHALF ? (A2 + sA * z) : nullptr;
    const __half* Bb = Bt + sB * z;
    float* Cf = OH ? nullptr : ((float*)C + sC * z);
    __half* Ch = OH ? ((__half*)C + sC * z) : nullptr;
    const int row0 = blockIdx.x * 128, col0 = blockIdx.y * 128;

    const int lane = tid & 31, wid = tid >> 5;
    const int wm = (wid >> 1) * 64, wn = (wid & 1) * 64;
    const int g = lane >> 2, tq = lane & 3;
    const int rL = tid >> 3, sec = tid & 7;
    const int nk = K / 64;

    const int g2 = lane >> 3, lr = lane & 7;
    const int aoff = (g2 & 1) * 8 + lr, aksel = g2 >> 1;
    const int boff = (g2 >> 1) * 8 + lr, bksel = g2 & 1;

    auto load = [&](int s, int k0) {
        const __half* Asrc;
        int kc;
        if (AHALF && k0 >= 256) { Asrc = Ab2; kc = k0 - 256 + sec * 8; }
        else { Asrc = Ab; kc = k0 + sec * 8; }
        uint32_t ab = sbase + s * 32768;
        uint32_t bb = ab + 16384;
#pragma unroll
        for (int i = 0; i < 8; i++) {
            int r = rL + i * 16;
            cp16(ab + r * 128 + ((sec ^ (r & 7)) * 16),
                 Asrc + (long)(row0 + r) * lda + kc);
        }
#pragma unroll
        for (int i = 0; i < 8; i++) {
            int r = rL + i * 16;
            cp16(bb + r * 128 + ((sec ^ (r & 7)) * 16),
                 Bb + (long)(col0 + r) * ldb + k0 + sec * 8);
        }
        CPCOMMIT;
    };

    float acc[4][8][4] = {};
    load(0, 0);
    load(1, 64);
    for (int kt = 0; kt < nk; kt++) {
        if (kt + 1 < nk) { CPWAIT1; } else { CPWAIT0; }
        __syncthreads();
        const uint32_t ab = sbase + (kt & 1) * 32768;
        const uint32_t bb = ab + 16384;
#pragma unroll
        for (int kw = 0; kw < 4; kw++) {
            uint32_t af[4][4], bf[8][2];
#pragma unroll
            for (int mi = 0; mi < 4; mi++) {
                int rr = wm + mi * 16 + aoff;
                uint32_t addr = ab + rr * 128 + (((kw * 2 + aksel) ^ lr) * 16);
                ldsm4(af[mi][0], af[mi][1], af[mi][2], af[mi][3], addr);
            }
#pragma unroll
            for (int np = 0; np < 4; np++) {
                int rr = wn + np * 16 + boff;
                uint32_t addr = bb + rr * 128 + (((kw * 2 + bksel) ^ lr) * 16);
                ldsm4(bf[2 * np][0], bf[2 * np][1], bf[2 * np + 1][0], bf[2 * np + 1][1], addr);
            }
#pragma unroll
            for (int mi = 0; mi < 4; mi++)
#pragma unroll
                for (int ni = 0; ni < 8; ni++) mma_f16(acc[mi][ni], af[mi], bf[ni]);
        }
        __syncthreads();
        if (kt + 2 < nk) load(kt & 1, (kt + 2) * 64);
    }
#pragma unroll
    for (int mi = 0; mi < 4; mi++) {
        int rr = row0 + wm + mi * 16 + g;
#pragma unroll
        for (int ni = 0; ni < 8; ni++) {
            int cc = col0 + wn + ni * 8 + tq * 2;
            float b0 = HB ? bias[cc] : 0.f, b1 = HB ? bias[cc + 1] : 0.f;
            float v0 = acc[mi][ni][0] + b0, v1 = acc[mi][ni][1] + b1;
            float v2 = acc[mi][ni][2] + b0, v3 = acc[mi][ni][3] + b1;
            if (OH) {
                *(uint32_t*)&Ch[(long)rr * ldc + cc] = pack2(v0, v1);
                *(uint32_t*)&Ch[(long)(rr + 8) * ldc + cc] = pack2(v2, v3);
            } else {
                Cf[(long)rr * ldc + cc] = v0;
                Cf[(long)rr * ldc + cc + 1] = v1;
                Cf[(long)(rr + 8) * ldc + cc] = v2;
                Cf[(long)(rr + 8) * ldc + cc + 1] = v3;
            }
        }
    }
}

// ---------------- grid barrier ----------------------------------------------
__device__ __forceinline__ void gridbar(unsigned nb, unsigned& mygen) {
    __syncthreads();
    if (threadIdx.x == 0) {
        __threadfence();
        unsigned old = atomicAdd(&g_barcnt, 1u);
        if (old == nb - 1) {
            g_barcnt = 0;
            __threadfence();
            atomicAdd((unsigned*)&g_bargen, 1u);
        } else {
            while (g_bargen <= mygen) {}
        }
        __threadfence();
    }
    __syncthreads();
    mygen++;
}

// ---------------- persistent LSTM: resident Whh, ldmatrix, fp16 Xp, BN stats -
__global__ void __launch_bounds__(256) k_lstm() {
    extern __shared__ uint32_t smL[];
    uint32_t* Bs = smL;                           // 256 x 128 u32 (swizzled)
    uint32_t* As = smL + 256 * 128;               // 64 x 128 u32 (swizzled)
    __half* Xp = (__half*)(smL + 256 * 128 + 64 * 128);  // 64 x 264 half

    const int tid = threadIdx.x;
    const int bid = blockIdx.x;
    const int rows0 = (bid >> 2) * 64, m0 = (bid & 3) * 64;
    const int b = rows0 >> 8, n0 = rows0 & 255;
    const int lane = tid & 31, wid = tid >> 5;
    const int g = lane >> 2, tq = lane & 3;
    const int wr = (wid >> 1) * 16;
    const int cbase = (wid & 1) * 128;
    const int r0 = wr + g, r1 = wr + g + 8;

    const int g2 = lane >> 3, lr = lane & 7;
    const int aoff = (g2 & 1) * 8 + lr, aksel = g2 >> 1;
    const int boff = (g2 >> 1) * 8 + lr, bksel = g2 & 1;

    const uint32_t bsb = (uint32_t)__cvta_generic_to_shared(Bs);
    const uint32_t asb = (uint32_t)__cvta_generic_to_shared(As);
    const uint32_t xpb = (uint32_t)__cvta_generic_to_shared(Xp);

    // ---- preload gathered Whh slice (once) ----
#pragma unroll
    for (int w = 0; w < 32; w++) {
        int idx = tid + w * 256;
        int c = idx >> 5, s = idx & 31;
        int n = c & 127, nw = c >> 7;
        int wrow = (n >> 5) * 256 + m0 + nw * 32 + (n & 31);
        cp16(bsb + (c * 128 + ((s ^ (c & 7)) << 2)) * 4,
             g_Whrh + (long)wrow * 256 + s * 8);
    }
    CPCOMMIT; CPWAIT0;
    __syncthreads();

    float creg[16];
#pragma unroll
    for (int i = 0; i < 16; i++) creg[i] = 0.f;
    float sreg[4][2] = {}, ssreg[4][2] = {};
    unsigned mygen = 0;

    const int arow = wr + aoff;
    const uint32_t abase = asb + arow * 512;
    const int amask = arow & 7;

    for (int t = 0; t < Ld; t++) {
        const long xz = ((long)b * Ld + t) * 256;

        if (t > 0) {
            const __half* Ab = g_th + (((long)b * Ld + (t - 1)) * 256 + n0) * 256;
#pragma unroll
            for (int w = 0; w < 8; w++) {
                int idx = tid + w * 256;
                int r = idx >> 5, s = idx & 31;
                cp16(asb + (r * 128 + ((s ^ (r & 7)) << 2)) * 4,
                     Ab + (long)r * 256 + s * 8);
            }
        }
        CPCOMMIT;
        // Xp (fp16): 64 rows x 256 halves, row stride 264
#pragma unroll
        for (int w = 0; w < 8; w++) {
            int idx = tid + w * 256;
            int r = idx >> 5, s = idx & 31;
            int gate = s >> 3, ms = (s & 7) * 8;
            cp16(xpb + (r * 264 + gate * 64 + ms) * 2,
                 g_xpjh + (xz + n0 + r) * 1024 + gate * 256 + m0 + ms);
        }
        CPCOMMIT;
        CPWAITG1;
        __syncthreads();

        float acc[16][4] = {};
        if (t > 0) {
#pragma unroll
            for (int j = 0; j < 16; j++) {
                uint32_t af[4];
                ldsm4(af[0], af[1], af[2], af[3],
                      abase + (((j * 2 + aksel) ^ amask) * 16));
#pragma unroll
                for (int np = 0; np < 8; np++) {
                    int col = cbase + np * 16 + boff;
                    uint32_t bf0[2], bf1[2];
                    ldsm4(bf0[0], bf0[1], bf1[0], bf1[1],
                          bsb + col * 512 + (((j * 2 + bksel) ^ (col & 7)) * 16));
                    mma_f16(acc[2 * np], af, bf0);
                    mma_f16(acc[2 * np + 1], af, bf1);
                }
            }
        }
        CPWAIT0;
        __syncthreads();

#pragma unroll
        for (int ni2 = 0; ni2 < 4; ni2++) {
            const int mloc = (wid & 1) * 32 + ni2 * 8 + tq * 2;
#pragma unroll
            for (int rs = 0; rs < 2; rs++) {
                const int lr2 = rs ? r1 : r0;
                const __half* xr = Xp + lr2 * 264 + mloc;
                float2 xi2 = __half22float2(*(const __half2*)(xr));
                float2 xf2 = __half22float2(*(const __half2*)(xr + 64));
                float2 xg2 = __half22float2(*(const __half2*)(xr + 128));
                float2 xo2 = __half22float2(*(const __half2*)(xr + 192));
                float hv[2];
#pragma unroll
                for (int col = 0; col < 2; col++) {
                    int ai = rs * 2 + col;
                    float zi = acc[ni2][ai] + (col ? xi2.y : xi2.x);
                    float zf = acc[4 + ni2][ai] + (col ? xf2.y : xf2.x);
                    float zg = acc[8 + ni2][ai] + (col ? xg2.y : xg2.x);
                    float zo = acc[12 + ni2][ai] + (col ? xo2.y : xo2.x);
                    int k = ni2 * 4 + ai;
                    float cc = sigf(zf) * creg[k] + sigf(zi) * tanhf(zg);
                    creg[k] = cc;
                    float h = sigf(zo) * tanhf(cc);
                    // BN stats use the rounded value actually stored
                    float hr = __half2float(__float2half_rn(h));
                    sreg[ni2][col] += hr;
                    ssreg[ni2][col] += hr * hr;
                    hv[col] = h;
                }
                *(uint32_t*)&g_th[(xz + n0 + lr2) * 256 + m0 + mloc] = pack2(hv[0], hv[1]);
            }
        }
        if (t < Ld - 1) gridbar(128, mygen);
    }

    // ---- BN stats reduction: block-local smem then global atomics ----
    __syncthreads();
    float* red = (float*)As;   // reuse (128 floats: [0:64) sum, [64:128) ssum)
    for (int i = tid; i < 128; i += 256) red[i] = 0.f;
    __syncthreads();
#pragma unroll
    for (int ni2 = 0; ni2 < 4; ni2++) {
#pragma unroll
        for (int col = 0; col < 2; col++) {
            int ml = (wid & 1) * 32 + ni2 * 8 + tq * 2 + col;
            atomicAdd(&red[ml], sreg[ni2][col]);
            atomicAdd(&red[64 + ml], ssreg[ni2][col]);
        }
    }
    __syncthreads();
    if (tid < 64) {
        atomicAdd(&g_sum[m0 + tid], (double)red[tid]);
        atomicAdd(&g_ssum[m0 + tid], (double)red[64 + tid]);
    }
}

// ---------------- BN finalize -------------------------------------------------
__global__ void k_finalize(const float* __restrict__ gamma, const float* __restrict__ beta) {
    int m = threadIdx.x;
    double mu = g_sum[m] / 65536.0;
    double var = g_ssum[m] / 65536.0 - mu * mu;
    float q = gamma[m] * (float)(1.0 / sqrt(var + 1e-5));
    g_q[m] = q;
    g_r0[m] = beta[m] - (float)mu * q;
}

// ---------------- launch ------------------------------------------------------
extern "C" void kernel_launch(void* const* d_in, const int* in_sizes, int n_in,
                              void* d_out, int out_size) {
    const float* X     = (const float*)d_in[0];
    const float* dis   = (const float*)d_in[1];
    const float* E1    = (const float*)d_in[2];
    const float* E2    = (const float*)d_in[3];
    const float* W_ih  = (const float*)d_in[4];
    const float* W_hh  = (const float*)d_in[5];
    const float* b_ih  = (const float*)d_in[6];
    const float* b_hh  = (const float*)d_in[7];
    const float* gamma = (const float*)d_in[8];
    const float* beta  = (const float*)d_in[9];
    const float* W_lin = (const float*)d_in[10];
    const float* b_lin = (const float*)d_in[11];
    float* out = (float*)d_out;

    const int GSMEM = 2 * 32768;                                   // 65536 B
    const int LSMEM = (256 * 128 + 64 * 128) * 4 + 64 * 264 * 2;   // 197632 B

    cudaFuncSetAttribute(kh<0, 0, 1>, cudaFuncAttributeMaxDynamicSharedMemorySize, GSMEM);
    cudaFuncSetAttribute(kh<1, 1, 1>, cudaFuncAttributeMaxDynamicSharedMemorySize, GSMEM);
    cudaFuncSetAttribute(kh<0, 1, 1>, cudaFuncAttributeMaxDynamicSharedMemorySize, GSMEM);
    cudaFuncSetAttribute(kh<0, 0, 0>, cudaFuncAttributeMaxDynamicSharedMemorySize, GSMEM);
    cudaFuncSetAttribute(k_lstm, cudaFuncAttributeMaxDynamicSharedMemorySize, LSMEM);

    __half *pXh, *pXwh, *pEch, *pWihh, *pWlinh, *pFch, *pTbh, *pPrh, *pXpjh;
    float *pBiasz;
    cudaGetSymbolAddress((void**)&pXh, g_Xh);
    cudaGetSymbolAddress((void**)&pXwh, g_Xwh);
    cudaGetSymbolAddress((void**)&pEch, g_Ech);
    cudaGetSymbolAddress((void**)&pWihh, g_Wihh);
    cudaGetSymbolAddress((void**)&pWlinh, g_Wlinh);
    cudaGetSymbolAddress((void**)&pFch, g_Fch);
    cudaGetSymbolAddress((void**)&pTbh, g_tbh);
    cudaGetSymbolAddress((void**)&pPrh, g_prh);
    cudaGetSymbolAddress((void**)&pXpjh, g_xpjh);
    cudaGetSymbolAddress((void**)&pBiasz, g_biasz);

    k_init<<<4, 256>>>(b_ih, b_hh);
    k_softmax<<<256, 256>>>(dis);
    k_prep<<<16384, 256>>>((const float4*)X, (const float4*)E1, (const float4*)E2,
                           (const float4*)W_ih, (const float4*)W_hh, (const float4*)W_lin);

    // Fcat
    kh<0, 0, 1><<<dim3(8, 2, 2), 128, GSMEM>>>(
        pWihh, nullptr, 256, 512, pEch, 65536, 256,
        pFch, 256, 512, nullptr, 256);

    // xproj = [Xh | Xwh] @ Fcat^T + biasz (K=512), fp16 out
    kh<1, 1, 1><<<dim3(2, 8, 256), 128, GSMEM>>>(
        pXh, pXwh, 65536, 256, pFch, 0, 512,
        pXpjh, 262144, 1024, pBiasz, 512);

    // persistent LSTM (fp16 Xp, fused BN stats)
    k_lstm<<<128, 256, LSMEM>>>();

    k_finalize<<<1, 256>>>(gamma, beta);
    k_affine<<<32768, 256>>>();

    // proj = tb @ Wlin^T + b_lin (half out)
    kh<0, 1, 1><<<dim3(2, 2, 256), 128, GSMEM>>>(
        pTbh, nullptr, 65536, 256, pWlinh, 0, 256,
        pPrh, 65536, 256, b_lin, 256);

    // out = proj @ tb^T (fp32 out)
    kh<0, 0, 0><<<dim3(2, 2, 256), 128, GSMEM>>>(
        pPrh, nullptr, 65536, 256, pTbh, 65536, 256,
        out, 65536, 256, nullptr, 256);
}

// round 15
// speedup vs baseline: 1.2195x; 1.0095x over previous
#include <cuda_runtime.h>
#include <cuda_fp16.h>
#include <cstdint>
#include <math.h>

#define Bd 8
#define Ld 32
#define HN ((size_t)Bd * Ld * 256 * 256)   // 16777216

// ---------------- device scratch ------------------------------------------
__device__ __align__(16) float g_w[256 * 256];
__device__ __align__(16) __half g_Xh[HN];
__device__ __align__(16) __half g_Xwh[HN];
__device__ __align__(16) __half g_Ech[2 * 256 * 256];
__device__ __align__(16) __half g_Wihh[1024 * 512];
__device__ __align__(16) __half g_Wlinh[256 * 256];
__device__ __align__(16) __half g_Whrh[1024 * 256];
__device__ __align__(16) __half g_Fch[1024 * 512];
__device__ __align__(16) __half g_th[HN];      // LSTM h
__device__ __align__(16) __half g_tbh[HN];     // batchnormed h
__device__ __align__(16) __half g_prh[HN];     // proj
__device__ __align__(16) __half g_xpjh[HN * 4];// xproj (fp16)
__device__ __align__(16) float g_biasz[1024];
__device__ double g_sum[256], g_ssum[256];
__device__ float g_q[256], g_r0[256];
// per-row-group barrier state, 128B padded per group
__device__ unsigned g_rgc[32 * 32];
__device__ volatile unsigned g_rgg[32 * 32];

// ---------------- helpers --------------------------------------------------
__device__ __forceinline__ uint32_t pack2(float a, float b) {
    __half2 h = __floats2half2_rn(a, b);
    return *(uint32_t*)&h;
}
__device__ __forceinline__ void mma_f16(float* d, const uint32_t* a, const uint32_t* b) {
    asm volatile(
        "mma.sync.aligned.m16n8k16.row.col.f32.f16.f16.f32 "
        "{%0,%1,%2,%3}, {%4,%5,%6,%7}, {%8,%9}, {%0,%1,%2,%3};\n"
        : "+f"(d[0]), "+f"(d[1]), "+f"(d[2]), "+f"(d[3])
        : "r"(a[0]), "r"(a[1]), "r"(a[2]), "r"(a[3]), "r"(b[0]), "r"(b[1]));
}
__device__ __forceinline__ void ldsm4(uint32_t& r0, uint32_t& r1, uint32_t& r2,
                                      uint32_t& r3, uint32_t addr) {
    asm volatile("ldmatrix.sync.aligned.m8n8.x4.shared.b16 {%0,%1,%2,%3}, [%4];"
                 : "=r"(r0), "=r"(r1), "=r"(r2), "=r"(r3) : "r"(addr));
}
__device__ __forceinline__ float sigf(float x) { return 1.f / (1.f + expf(-x)); }

__device__ __forceinline__ void cp16(uint32_t s, const void* g) {
    asm volatile("cp.async.cg.shared.global [%0], [%1], 16;" :: "r"(s), "l"(g));
}
#define CPCOMMIT asm volatile("cp.async.commit_group;")
#define CPWAITG1 asm volatile("cp.async.wait_group 1;")
#define CPWAIT1 asm volatile("cp.async.wait_group 1;")
#define CPWAIT0 asm volatile("cp.async.wait_group 0;")

// ---------------- init ------------------------------------------------------
__global__ void k_init(const float* __restrict__ bih, const float* __restrict__ bhh) {
    int i = blockIdx.x * 256 + threadIdx.x;  // grid 4 -> 1024 threads
    g_biasz[i] = bih[i] + bhh[i];
    if (i < 256) { g_sum[i] = 0.0; g_ssum[i] = 0.0; }
    g_rgc[i] = 0;
    g_rgg[i] = 0;
}

// ---------------- softmax of -dis, row-wise ---------------------------------
__global__ void k_softmax(const float* __restrict__ dis) {
    __shared__ float red[256];
    int o = blockIdx.x, t = threadIdx.x;
    float e = expf(-dis[o * 256 + t]);
    red[t] = e;
    __syncthreads();
    for (int s = 128; s > 0; s >>= 1) {
        if (t < s) red[t] += red[t + s];
        __syncthreads();
    }
    g_w[o * 256 + t] = e / red[0];
}

// ---------------- prep: fp16 operand copies ---------------------------------
__global__ void k_prep(const float4* __restrict__ X, const float4* __restrict__ E1,
                       const float4* __restrict__ E2, const float4* __restrict__ W_ih,
                       const float4* __restrict__ W_hh, const float4* __restrict__ W_lin) {
    long i = (long)blockIdx.x * 256 + threadIdx.x;  // grid 16384
    int nd = (int)(i & 16383);
    float4 x = X[i];
    float4 w = ((const float4*)g_w)[nd];
    ((uint2*)g_Xh)[i] = make_uint2(pack2(x.x, x.y), pack2(x.z, x.w));
    ((uint2*)g_Xwh)[i] = make_uint2(pack2(x.x * w.x, x.y * w.y), pack2(x.z * w.z, x.w * w.w));
    if (i < 32768) {
        float4 e = (i < 16384) ? E1[i] : E2[i - 16384];
        ((uint2*)g_Ech)[i] = make_uint2(pack2(e.x, e.y), pack2(e.z, e.w));
    }
    if (i < 131072) {
        float4 v = W_ih[i];
        ((uint2*)g_Wihh)[i] = make_uint2(pack2(v.x, v.y), pack2(v.z, v.w));
    }
    if (i < 65536) {
        float4 v = W_hh[i];
        ((uint2*)g_Whrh)[i] = make_uint2(pack2(v.x, v.y), pack2(v.z, v.w));
    }
    if (i < 16384) {
        float4 v = W_lin[i];
        ((uint2*)g_Wlinh)[i] = make_uint2(pack2(v.x, v.y), pack2(v.z, v.w));
    }
}

// ---------------- tb = half(q*h + r0) ----------------------------------------
__global__ void k_affine() {
    long i = (long)blockIdx.x * 256 + threadIdx.x;  // grid 32768
    uint32_t u = ((const uint32_t*)g_th)[i];
    __half2 h2 = *(__half2*)&u;
    float2 f = __half22float2(h2);
    int c = (int)((i * 2) & 255);
    f.x = f.x * g_q[c] + g_r0[c];
    f.y = f.y * g_q[c + 1] + g_r0[c + 1];
    ((uint32_t*)g_tbh)[i] = pack2(f.x, f.y);
}

// ---------------- 128x128 fp16 GEMM with ldmatrix fragments ------------------
template <int AHALF, int HB, int OH>
__global__ void __launch_bounds__(128, 2) kh(
    const __half* __restrict__ A, const __half* __restrict__ A2, long sA, int lda,
    const __half* __restrict__ Bt, long sB, int ldb,
    void* __restrict__ C, long sC, int ldc,
    const float* __restrict__ bias, int K) {
    extern __shared__ uint32_t smu[];
    const uint32_t sbase = (uint32_t)__cvta_generic_to_shared(smu);

    const int tid = threadIdx.x;
    const int z = blockIdx.z;
    const __half* Ab = A + sA * z;
    const __half* Ab2 = AHALF ? (A2 + sA * z) : nullptr;
    const __half* Bb = Bt + sB * z;
    float* Cf = OH ? nullptr : ((float*)C + sC * z);
    __half* Ch = OH ? ((__half*)C + sC * z) : nullptr;
    const int row0 = blockIdx.x * 128, col0 = blockIdx.y * 128;

    const int lane = tid & 31, wid = tid >> 5;
    const int wm = (wid >> 1) * 64, wn = (wid & 1) * 64;
    const int g = lane >> 2, tq = lane & 3;
    const int rL = tid >> 3, sec = tid & 7;
    const int nk = K / 64;

    const int g2 = lane >> 3, lr = lane & 7;
    const int aoff = (g2 & 1) * 8 + lr, aksel = g2 >> 1;
    const int boff = (g2 >> 1) * 8 + lr, bksel = g2 & 1;

    auto load = [&](int s, int k0) {
        const __half* Asrc;
        int kc;
        if (AHALF && k0 >= 256) { Asrc = Ab2; kc = k0 - 256 + sec * 8; }
        else { Asrc = Ab; kc = k0 + sec * 8; }
        uint32_t ab = sbase + s * 32768;
        uint32_t bb = ab + 16384;
#pragma unroll
        for (int i = 0; i < 8; i++) {
            int r = rL + i * 16;
            cp16(ab + r * 128 + ((sec ^ (r & 7)) * 16),
                 Asrc + (long)(row0 + r) * lda + kc);
        }
#pragma unroll
        for (int i = 0; i < 8; i++) {
            int r = rL + i * 16;
            cp16(bb + r * 128 + ((sec ^ (r & 7)) * 16),
                 Bb + (long)(col0 + r) * ldb + k0 + sec * 8);
        }
        CPCOMMIT;
    };

    float acc[4][8][4] = {};
    load(0, 0);
    load(1, 64);
    for (int kt = 0; kt < nk; kt++) {
        if (kt + 1 < nk) { CPWAIT1; } else { CPWAIT0; }
        __syncthreads();
        const uint32_t ab = sbase + (kt & 1) * 32768;
        const uint32_t bb = ab + 16384;
#pragma unroll
        for (int kw = 0; kw < 4; kw++) {
            uint32_t af[4][4], bf[8][2];
#pragma unroll
            for (int mi = 0; mi < 4; mi++) {
                int rr = wm + mi * 16 + aoff;
                uint32_t addr = ab + rr * 128 + (((kw * 2 + aksel) ^ lr) * 16);
                ldsm4(af[mi][0], af[mi][1], af[mi][2], af[mi][3], addr);
            }
#pragma unroll
            for (int np = 0; np < 4; np++) {
                int rr = wn + np * 16 + boff;
                uint32_t addr = bb + rr * 128 + (((kw * 2 + bksel) ^ lr) * 16);
                ldsm4(bf[2 * np][0], bf[2 * np][1], bf[2 * np + 1][0], bf[2 * np + 1][1], addr);
            }
#pragma unroll
            for (int mi = 0; mi < 4; mi++)
#pragma unroll
                for (int ni = 0; ni < 8; ni++) mma_f16(acc[mi][ni], af[mi], bf[ni]);
        }
        __syncthreads();
        if (kt + 2 < nk) load(kt & 1, (kt + 2) * 64);
    }
#pragma unroll
    for (int mi = 0; mi < 4; mi++) {
        int rr = row0 + wm + mi * 16 + g;
#pragma unroll
        for (int ni = 0; ni < 8; ni++) {
            int cc = col0 + wn + ni * 8 + tq * 2;
            float b0 = HB ? bias[cc] : 0.f, b1 = HB ? bias[cc + 1] : 0.f;
            float v0 = acc[mi][ni][0] + b0, v1 = acc[mi][ni][1] + b1;
            float v2 = acc[mi][ni][2] + b0, v3 = acc[mi][ni][3] + b1;
            if (OH) {
                *(uint32_t*)&Ch[(long)rr * ldc + cc] = pack2(v0, v1);
                *(uint32_t*)&Ch[(long)(rr + 8) * ldc + cc] = pack2(v2, v3);
            } else {
                Cf[(long)rr * ldc + cc] = v0;
                Cf[(long)rr * ldc + cc + 1] = v1;
                Cf[(long)(rr + 8) * ldc + cc] = v2;
                Cf[(long)(rr + 8) * ldc + cc + 1] = v3;
            }
        }
    }
}

// ---------------- row-group barrier (4 blocks, 128B-padded state) ------------
__device__ __forceinline__ void rgbar(int rg, unsigned& mygen) {
    __syncthreads();
    if (threadIdx.x == 0) {
        __threadfence();
        unsigned* cnt = &g_rgc[rg * 32];
        volatile unsigned* gen = &g_rgg[rg * 32];
        unsigned old = atomicAdd(cnt, 1u);
        if (old == 3u) {
            *cnt = 0;
            __threadfence();
            atomicAdd((unsigned*)gen, 1u);
        } else {
            while (*gen <= mygen) {}
        }
        __threadfence();
    }
    __syncthreads();
    mygen++;
}

// ---------------- persistent LSTM: resident Whh, ldmatrix, fp16 Xp, BN stats -
__global__ void __launch_bounds__(256) k_lstm() {
    extern __shared__ uint32_t smL[];
    uint32_t* Bs = smL;                           // 256 x 128 u32 (swizzled)
    uint32_t* As = smL + 256 * 128;               // 64 x 128 u32 (swizzled)
    __half* Xp = (__half*)(smL + 256 * 128 + 64 * 128);  // 64 x 264 half

    const int tid = threadIdx.x;
    const int bid = blockIdx.x;
    const int rg = bid >> 2;
    const int rows0 = rg * 64, m0 = (bid & 3) * 64;
    const int b = rows0 >> 8, n0 = rows0 & 255;
    const int lane = tid & 31, wid = tid >> 5;
    const int g = lane >> 2, tq = lane & 3;
    const int wr = (wid >> 1) * 16;
    const int cbase = (wid & 1) * 128;
    const int r0 = wr + g, r1 = wr + g + 8;

    const int g2 = lane >> 3, lr = lane & 7;
    const int aoff = (g2 & 1) * 8 + lr, aksel = g2 >> 1;
    const int boff = (g2 >> 1) * 8 + lr, bksel = g2 & 1;

    const uint32_t bsb = (uint32_t)__cvta_generic_to_shared(Bs);
    const uint32_t asb = (uint32_t)__cvta_generic_to_shared(As);
    const uint32_t xpb = (uint32_t)__cvta_generic_to_shared(Xp);

    // ---- preload gathered Whh slice (once) ----
#pragma unroll
    for (int w = 0; w < 32; w++) {
        int idx = tid + w * 256;
        int c = idx >> 5, s = idx & 31;
        int n = c & 127, nw = c >> 7;
        int wrow = (n >> 5) * 256 + m0 + nw * 32 + (n & 31);
        cp16(bsb + (c * 128 + ((s ^ (c & 7)) << 2)) * 4,
             g_Whrh + (long)wrow * 256 + s * 8);
    }
    CPCOMMIT; CPWAIT0;
    __syncthreads();

    float creg[16];
#pragma unroll
    for (int i = 0; i < 16; i++) creg[i] = 0.f;
    float sreg[4][2] = {}, ssreg[4][2] = {};
    unsigned mygen = 0;

    const int arow = wr + aoff;
    const uint32_t abase = asb + arow * 512;
    const int amask = arow & 7;

    for (int t = 0; t < Ld; t++) {
        const long xz = ((long)b * Ld + t) * 256;

        if (t > 0) {
            const __half* Ab = g_th + (((long)b * Ld + (t - 1)) * 256 + n0) * 256;
#pragma unroll
            for (int w = 0; w < 8; w++) {
                int idx = tid + w * 256;
                int r = idx >> 5, s = idx & 31;
                cp16(asb + (r * 128 + ((s ^ (r & 7)) << 2)) * 4,
                     Ab + (long)r * 256 + s * 8);
            }
        }
        CPCOMMIT;
        // Xp (fp16): 64 rows x 256 halves, row stride 264
#pragma unroll
        for (int w = 0; w < 8; w++) {
            int idx = tid + w * 256;
            int r = idx >> 5, s = idx & 31;
            int gate = s >> 3, ms = (s & 7) * 8;
            cp16(xpb + (r * 264 + gate * 64 + ms) * 2,
                 g_xpjh + (xz + n0 + r) * 1024 + gate * 256 + m0 + ms);
        }
        CPCOMMIT;
        CPWAITG1;
        __syncthreads();

        float acc[16][4] = {};
        if (t > 0) {
#pragma unroll
            for (int j = 0; j < 16; j++) {
                uint32_t af[4];
                ldsm4(af[0], af[1], af[2], af[3],
                      abase + (((j * 2 + aksel) ^ amask) * 16));
#pragma unroll
                for (int np = 0; np < 8; np++) {
                    int col = cbase + np * 16 + boff;
                    uint32_t bf0[2], bf1[2];
                    ldsm4(bf0[0], bf0[1], bf1[0], bf1[1],
                          bsb + col * 512 + (((j * 2 + bksel) ^ (col & 7)) * 16));
                    mma_f16(acc[2 * np], af, bf0);
                    mma_f16(acc[2 * np + 1], af, bf1);
                }
            }
        }
        CPWAIT0;
        __syncthreads();

#pragma unroll
        for (int ni2 = 0; ni2 < 4; ni2++) {
            const int mloc = (wid & 1) * 32 + ni2 * 8 + tq * 2;
#pragma unroll
            for (int rs = 0; rs < 2; rs++) {
                const int lr2 = rs ? r1 : r0;
                const __half* xr = Xp + lr2 * 264 + mloc;
                float2 xi2 = __half22float2(*(const __half2*)(xr));
                float2 xf2 = __half22float2(*(const __half2*)(xr + 64));
                float2 xg2 = __half22float2(*(const __half2*)(xr + 128));
                float2 xo2 = __half22float2(*(const __half2*)(xr + 192));
                float hv[2];
#pragma unroll
                for (int col = 0; col < 2; col++) {
                    int ai = rs * 2 + col;
                    float zi = acc[ni2][ai] + (col ? xi2.y : xi2.x);
                    float zf = acc[4 + ni2][ai] + (col ? xf2.y : xf2.x);
                    float zg = acc[8 + ni2][ai] + (col ? xg2.y : xg2.x);
                    float zo = acc[12 + ni2][ai] + (col ? xo2.y : xo2.x);
                    int k = ni2 * 4 + ai;
                    float cc = sigf(zf) * creg[k] + sigf(zi) * tanhf(zg);
                    creg[k] = cc;
                    float h = sigf(zo) * tanhf(cc);
                    float hr = __half2float(__float2half_rn(h));
                    sreg[ni2][col] += hr;
                    ssreg[ni2][col] += hr * hr;
                    hv[col] = h;
                }
                *(uint32_t*)&g_th[(xz + n0 + lr2) * 256 + m0 + mloc] = pack2(hv[0], hv[1]);
            }
        }
        if (t < Ld - 1) rgbar(rg, mygen);
    }

    // ---- BN stats reduction: block-local smem then global atomics ----
    __syncthreads();
    float* red = (float*)As;
    for (int i = tid; i < 128; i += 256) red[i] = 0.f;
    __syncthreads();
#pragma unroll
    for (int ni2 = 0; ni2 < 4; ni2++) {
#pragma unroll
        for (int col = 0; col < 2; col++) {
            int ml = (wid & 1) * 32 + ni2 * 8 + tq * 2 + col;
            atomicAdd(&red[ml], sreg[ni2][col]);
            atomicAdd(&red[64 + ml], ssreg[ni2][col]);
        }
    }
    __syncthreads();
    if (tid < 64) {
        atomicAdd(&g_sum[m0 + tid], (double)red[tid]);
        atomicAdd(&g_ssum[m0 + tid], (double)red[64 + tid]);
    }
}

// ---------------- BN finalize -------------------------------------------------
__global__ void k_finalize(const float* __restrict__ gamma, const float* __restrict__ beta) {
    int m = threadIdx.x;
    double mu = g_sum[m] / 65536.0;
    double var = g_ssum[m] / 65536.0 - mu * mu;
    float q = gamma[m] * (float)(1.0 / sqrt(var + 1e-5));
    g_q[m] = q;
    g_r0[m] = beta[m] - (float)mu * q;
}

// ---------------- launch ------------------------------------------------------
extern "C" void kernel_launch(void* const* d_in, const int* in_sizes, int n_in,
                              void* d_out, int out_size) {
    const float* X     = (const float*)d_in[0];
    const float* dis   = (const float*)d_in[1];
    const float* E1    = (const float*)d_in[2];
    const float* E2    = (const float*)d_in[3];
    const float* W_ih  = (const float*)d_in[4];
    const float* W_hh  = (const float*)d_in[5];
    const float* b_ih  = (const float*)d_in[6];
    const float* b_hh  = (const float*)d_in[7];
    const float* gamma = (const float*)d_in[8];
    const float* beta  = (const float*)d_in[9];
    const float* W_lin = (const float*)d_in[10];
    const float* b_lin = (const float*)d_in[11];
    float* out = (float*)d_out;

    const int GSMEM = 2 * 32768;                                   // 65536 B
    const int LSMEM = (256 * 128 + 64 * 128) * 4 + 64 * 264 * 2;   // 197632 B

    cudaFuncSetAttribute(kh<0, 0, 1>, cudaFuncAttributeMaxDynamicSharedMemorySize, GSMEM);
    cudaFuncSetAttribute(kh<1, 1, 1>, cudaFuncAttributeMaxDynamicSharedMemorySize, GSMEM);
    cudaFuncSetAttribute(kh<0, 1, 1>, cudaFuncAttributeMaxDynamicSharedMemorySize, GSMEM);
    cudaFuncSetAttribute(kh<0, 0, 0>, cudaFuncAttributeMaxDynamicSharedMemorySize, GSMEM);
    cudaFuncSetAttribute(k_lstm, cudaFuncAttributeMaxDynamicSharedMemorySize, LSMEM);

    __half *pXh, *pXwh, *pEch, *pWihh, *pWlinh, *pFch, *pTbh, *pPrh, *pXpjh;
    float *pBiasz;
    cudaGetSymbolAddress((void**)&pXh, g_Xh);
    cudaGetSymbolAddress((void**)&pXwh, g_Xwh);
    cudaGetSymbolAddress((void**)&pEch, g_Ech);
    cudaGetSymbolAddress((void**)&pWihh, g_Wihh);
    cudaGetSymbolAddress((void**)&pWlinh, g_Wlinh);
    cudaGetSymbolAddress((void**)&pFch, g_Fch);
    cudaGetSymbolAddress((void**)&pTbh, g_tbh);
    cudaGetSymbolAddress((void**)&pPrh, g_prh);
    cudaGetSymbolAddress((void**)&pXpjh, g_xpjh);
    cudaGetSymbolAddress((void**)&pBiasz, g_biasz);

    k_init<<<4, 256>>>(b_ih, b_hh);
    k_softmax<<<256, 256>>>(dis);
    k_prep<<<16384, 256>>>((const float4*)X, (const float4*)E1, (const float4*)E2,
                           (const float4*)W_ih, (const float4*)W_hh, (const float4*)W_lin);

    // Fcat
    kh<0, 0, 1><<<dim3(8, 2, 2), 128, GSMEM>>>(
        pWihh, nullptr, 256, 512, pEch, 65536, 256,
        pFch, 256, 512, nullptr, 256);

    // xproj = [Xh | Xwh] @ Fcat^T + biasz (K=512), fp16 out
    kh<1, 1, 1><<<dim3(2, 8, 256), 128, GSMEM>>>(
        pXh, pXwh, 65536, 256, pFch, 0, 512,
        pXpjh, 262144, 1024, pBiasz, 512);

    // persistent LSTM (row-group barriers, fp16 Xp, fused BN stats)
    k_lstm<<<128, 256, LSMEM>>>();

    k_finalize<<<1, 256>>>(gamma, beta);
    k_affine<<<32768, 256>>>();

    // proj = tb @ Wlin^T + b_lin (half out)
    kh<0, 1, 1><<<dim3(2, 2, 256), 128, GSMEM>>>(
        pTbh, nullptr, 65536, 256, pWlinh, 0, 256,
        pPrh, 65536, 256, b_lin, 256);

    // out = proj @ tb^T (fp32 out)
    kh<0, 0, 0><<<dim3(2, 2, 256), 128, GSMEM>>>(
        pPrh, nullptr, 65536, 256, pTbh, 65536, 256,
        out, 65536, 256, nullptr, 256);
}

// round 16
// speedup vs baseline: 1.2266x; 1.0058x over previous
#include <cuda_runtime.h>
#include <cuda_fp16.h>
#include <cstdint>
#include <math.h>

#define Bd 8
#define Ld 32
#define HN ((size_t)Bd * Ld * 256 * 256)   // 16777216

// ---------------- device scratch ------------------------------------------
__device__ __align__(16) float g_w[256 * 256];
__device__ __align__(16) __half g_Xh[HN];
__device__ __align__(16) __half g_Xwh[HN];
__device__ __align__(16) __half g_Ech[2 * 256 * 256];
__device__ __align__(16) __half g_Wihh[1024 * 512];
__device__ __align__(16) __half g_Wlinh[256 * 256];
__device__ __align__(16) __half g_Whrh[1024 * 256];
__device__ __align__(16) __half g_Fch[1024 * 512];
__device__ __align__(16) __half g_th[HN];      // LSTM h
__device__ __align__(16) __half g_tbh[HN];     // batchnormed h
__device__ __align__(16) __half g_prh[HN];     // proj
__device__ __align__(16) __half g_xpjh[HN * 4];// xproj (fp16)
__device__ __align__(16) float g_biasz[1024];
__device__ double g_sum[256], g_ssum[256];
__device__ float g_q[256], g_r0[256];
// per-row-group barrier state, 128B padded per group
__device__ unsigned g_rgc[32 * 32];
__device__ volatile unsigned g_rgg[32 * 32];

// ---------------- helpers --------------------------------------------------
__device__ __forceinline__ uint32_t pack2(float a, float b) {
    __half2 h = __floats2half2_rn(a, b);
    return *(uint32_t*)&h;
}
__device__ __forceinline__ void mma_f16(float* d, const uint32_t* a, const uint32_t* b) {
    asm volatile(
        "mma.sync.aligned.m16n8k16.row.col.f32.f16.f16.f32 "
        "{%0,%1,%2,%3}, {%4,%5,%6,%7}, {%8,%9}, {%0,%1,%2,%3};\n"
        : "+f"(d[0]), "+f"(d[1]), "+f"(d[2]), "+f"(d[3])
        : "r"(a[0]), "r"(a[1]), "r"(a[2]), "r"(a[3]), "r"(b[0]), "r"(b[1]));
}
__device__ __forceinline__ void ldsm4(uint32_t& r0, uint32_t& r1, uint32_t& r2,
                                      uint32_t& r3, uint32_t addr) {
    asm volatile("ldmatrix.sync.aligned.m8n8.x4.shared.b16 {%0,%1,%2,%3}, [%4];"
                 : "=r"(r0), "=r"(r1), "=r"(r2), "=r"(r3) : "r"(addr));
}
__device__ __forceinline__ float sigf(float x) { return 1.f / (1.f + expf(-x)); }

__device__ __forceinline__ void cp16(uint32_t s, const void* g) {
    asm volatile("cp.async.cg.shared.global [%0], [%1], 16;" :: "r"(s), "l"(g));
}
#define CPCOMMIT asm volatile("cp.async.commit_group;")
#define CPWAITG1 asm volatile("cp.async.wait_group 1;")
#define CPWAIT2 asm volatile("cp.async.wait_group 2;")
#define CPWAIT1 asm volatile("cp.async.wait_group 1;")
#define CPWAIT0 asm volatile("cp.async.wait_group 0;")

// ---------------- softmax + init (merged: one fewer launch) ------------------
__global__ void k_softmax(const float* __restrict__ dis, const float* __restrict__ bih,
                          const float* __restrict__ bhh) {
    __shared__ float red[256];
    int o = blockIdx.x, t = threadIdx.x;
    float e = expf(-dis[o * 256 + t]);
    red[t] = e;
    if (o < 4) {
        int i = o * 256 + t;
        g_biasz[i] = bih[i] + bhh[i];
        if (i < 256) { g_sum[i] = 0.0; g_ssum[i] = 0.0; }
        g_rgc[i] = 0;
        g_rgg[i] = 0;
    }
    __syncthreads();
    for (int s = 128; s > 0; s >>= 1) {
        if (t < s) red[t] += red[t + s];
        __syncthreads();
    }
    g_w[o * 256 + t] = e / red[0];
}

// ---------------- prep: fp16 operand copies ---------------------------------
__global__ void k_prep(const float4* __restrict__ X, const float4* __restrict__ E1,
                       const float4* __restrict__ E2, const float4* __restrict__ W_ih,
                       const float4* __restrict__ W_hh, const float4* __restrict__ W_lin) {
    long i = (long)blockIdx.x * 256 + threadIdx.x;  // grid 16384
    int nd = (int)(i & 16383);
    float4 x = X[i];
    float4 w = ((const float4*)g_w)[nd];
    ((uint2*)g_Xh)[i] = make_uint2(pack2(x.x, x.y), pack2(x.z, x.w));
    ((uint2*)g_Xwh)[i] = make_uint2(pack2(x.x * w.x, x.y * w.y), pack2(x.z * w.z, x.w * w.w));
    if (i < 32768) {
        float4 e = (i < 16384) ? E1[i] : E2[i - 16384];
        ((uint2*)g_Ech)[i] = make_uint2(pack2(e.x, e.y), pack2(e.z, e.w));
    }
    if (i < 131072) {
        float4 v = W_ih[i];
        ((uint2*)g_Wihh)[i] = make_uint2(pack2(v.x, v.y), pack2(v.z, v.w));
    }
    if (i < 65536) {
        float4 v = W_hh[i];
        ((uint2*)g_Whrh)[i] = make_uint2(pack2(v.x, v.y), pack2(v.z, v.w));
    }
    if (i < 16384) {
        float4 v = W_lin[i];
        ((uint2*)g_Wlinh)[i] = make_uint2(pack2(v.x, v.y), pack2(v.z, v.w));
    }
}

// ---------------- tb = half(q*h + r0) ----------------------------------------
__global__ void k_affine() {
    long i = (long)blockIdx.x * 256 + threadIdx.x;  // grid 32768
    uint32_t u = ((const uint32_t*)g_th)[i];
    __half2 h2 = *(__half2*)&u;
    float2 f = __half22float2(h2);
    int c = (int)((i * 2) & 255);
    f.x = f.x * g_q[c] + g_r0[c];
    f.y = f.y * g_q[c + 1] + g_r0[c + 1];
    ((uint32_t*)g_tbh)[i] = pack2(f.x, f.y);
}

// ---------------- 128x128 fp16 GEMM, ldmatrix, 3-stage cp.async --------------
// Smem: 3 stages x (A 16KB + B 16KB) = 96KB; 2 blocks/SM.
template <int AHALF, int HB, int OH>
__global__ void __launch_bounds__(128, 2) kh(
    const __half* __restrict__ A, const __half* __restrict__ A2, long sA, int lda,
    const __half* __restrict__ Bt, long sB, int ldb,
    void* __restrict__ C, long sC, int ldc,
    const float* __restrict__ bias, int K) {
    extern __shared__ uint32_t smu[];
    const uint32_t sbase = (uint32_t)__cvta_generic_to_shared(smu);

    const int tid = threadIdx.x;
    const int z = blockIdx.z;
    const __half* Ab = A + sA * z;
    const __half* Ab2 = AHALF ? (A2 + sA * z) : nullptr;
    const __half* Bb = Bt + sB * z;
    float* Cf = OH ? nullptr : ((float*)C + sC * z);
    __half* Ch = OH ? ((__half*)C + sC * z) : nullptr;
    const int row0 = blockIdx.x * 128, col0 = blockIdx.y * 128;

    const int lane = tid & 31, wid = tid >> 5;
    const int wm = (wid >> 1) * 64, wn = (wid & 1) * 64;
    const int g = lane >> 2, tq = lane & 3;
    const int rL = tid >> 3, sec = tid & 7;
    const int nk = K / 64;

    const int g2 = lane >> 3, lr = lane & 7;
    const int aoff = (g2 & 1) * 8 + lr, aksel = g2 >> 1;
    const int boff = (g2 >> 1) * 8 + lr, bksel = g2 & 1;

    auto load = [&](int stg, int k0) {
        const __half* Asrc;
        int kc;
        if (AHALF && k0 >= 256) { Asrc = Ab2; kc = k0 - 256 + sec * 8; }
        else { Asrc = Ab; kc = k0 + sec * 8; }
        uint32_t ab = sbase + stg * 32768;
        uint32_t bb = ab + 16384;
#pragma unroll
        for (int i = 0; i < 8; i++) {
            int r = rL + i * 16;
            cp16(ab + r * 128 + ((sec ^ (r & 7)) * 16),
                 Asrc + (long)(row0 + r) * lda + kc);
        }
#pragma unroll
        for (int i = 0; i < 8; i++) {
            int r = rL + i * 16;
            cp16(bb + r * 128 + ((sec ^ (r & 7)) * 16),
                 Bb + (long)(col0 + r) * ldb + k0 + sec * 8);
        }
        CPCOMMIT;
    };

    float acc[4][8][4] = {};
    load(0, 0);
    load(1, 64);
    for (int kt = 0; kt < nk; kt++) {
        if (kt + 2 < nk) { load((kt + 2) % 3, (kt + 2) * 64); CPWAIT2; }
        else if (kt + 1 < nk) { CPWAIT1; }
        else { CPWAIT0; }
        __syncthreads();
        const uint32_t ab = sbase + (kt % 3) * 32768;
        const uint32_t bb = ab + 16384;
#pragma unroll
        for (int kw = 0; kw < 4; kw++) {
            uint32_t af[4][4], bf[8][2];
#pragma unroll
            for (int mi = 0; mi < 4; mi++) {
                int rr = wm + mi * 16 + aoff;
                uint32_t addr = ab + rr * 128 + (((kw * 2 + aksel) ^ lr) * 16);
                ldsm4(af[mi][0], af[mi][1], af[mi][2], af[mi][3], addr);
            }
#pragma unroll
            for (int np = 0; np < 4; np++) {
                int rr = wn + np * 16 + boff;
                uint32_t addr = bb + rr * 128 + (((kw * 2 + bksel) ^ lr) * 16);
                ldsm4(bf[2 * np][0], bf[2 * np][1], bf[2 * np + 1][0], bf[2 * np + 1][1], addr);
            }
#pragma unroll
            for (int mi = 0; mi < 4; mi++)
#pragma unroll
                for (int ni = 0; ni < 8; ni++) mma_f16(acc[mi][ni], af[mi], bf[ni]);
        }
        __syncthreads();
    }
#pragma unroll
    for (int mi = 0; mi < 4; mi++) {
        int rr = row0 + wm + mi * 16 + g;
#pragma unroll
        for (int ni = 0; ni < 8; ni++) {
            int cc = col0 + wn + ni * 8 + tq * 2;
            float b0 = HB ? bias[cc] : 0.f, b1 = HB ? bias[cc + 1] : 0.f;
            float v0 = acc[mi][ni][0] + b0, v1 = acc[mi][ni][1] + b1;
            float v2 = acc[mi][ni][2] + b0, v3 = acc[mi][ni][3] + b1;
            if (OH) {
                *(uint32_t*)&Ch[(long)rr * ldc + cc] = pack2(v0, v1);
                *(uint32_t*)&Ch[(long)(rr + 8) * ldc + cc] = pack2(v2, v3);
            } else {
                Cf[(long)rr * ldc + cc] = v0;
                Cf[(long)rr * ldc + cc + 1] = v1;
                Cf[(long)(rr + 8) * ldc + cc] = v2;
                Cf[(long)(rr + 8) * ldc + cc + 1] = v3;
            }
        }
    }
}

// ---------------- row-group barrier (4 blocks, 128B-padded state) ------------
__device__ __forceinline__ void rgbar(int rg, unsigned& mygen) {
    __syncthreads();
    if (threadIdx.x == 0) {
        __threadfence();
        unsigned* cnt = &g_rgc[rg * 32];
        volatile unsigned* gen = &g_rgg[rg * 32];
        unsigned old = atomicAdd(cnt, 1u);
        if (old == 3u) {
            *cnt = 0;
            __threadfence();
            atomicAdd((unsigned*)gen, 1u);
        } else {
            while (*gen <= mygen) {}
        }
        __threadfence();
    }
    __syncthreads();
    mygen++;
}

// ---------------- persistent LSTM: resident Whh, ldmatrix, fp16 Xp, BN stats -
__global__ void __launch_bounds__(256) k_lstm() {
    extern __shared__ uint32_t smL[];
    uint32_t* Bs = smL;                           // 256 x 128 u32 (swizzled)
    uint32_t* As = smL + 256 * 128;               // 64 x 128 u32 (swizzled)
    __half* Xp = (__half*)(smL + 256 * 128 + 64 * 128);  // 64 x 264 half

    const int tid = threadIdx.x;
    const int bid = blockIdx.x;
    const int rg = bid >> 2;
    const int rows0 = rg * 64, m0 = (bid & 3) * 64;
    const int b = rows0 >> 8, n0 = rows0 & 255;
    const int lane = tid & 31, wid = tid >> 5;
    const int g = lane >> 2, tq = lane & 3;
    const int wr = (wid >> 1) * 16;
    const int cbase = (wid & 1) * 128;
    const int r0 = wr + g, r1 = wr + g + 8;

    const int g2 = lane >> 3, lr = lane & 7;
    const int aoff = (g2 & 1) * 8 + lr, aksel = g2 >> 1;
    const int boff = (g2 >> 1) * 8 + lr, bksel = g2 & 1;

    const uint32_t bsb = (uint32_t)__cvta_generic_to_shared(Bs);
    const uint32_t asb = (uint32_t)__cvta_generic_to_shared(As);
    const uint32_t xpb = (uint32_t)__cvta_generic_to_shared(Xp);

    // ---- preload gathered Whh slice (once) ----
#pragma unroll
    for (int w = 0; w < 32; w++) {
        int idx = tid + w * 256;
        int c = idx >> 5, s = idx & 31;
        int n = c & 127, nw = c >> 7;
        int wrow = (n >> 5) * 256 + m0 + nw * 32 + (n & 31);
        cp16(bsb + (c * 128 + ((s ^ (c & 7)) << 2)) * 4,
             g_Whrh + (long)wrow * 256 + s * 8);
    }
    CPCOMMIT; CPWAIT0;
    __syncthreads();

    float creg[16];
#pragma unroll
    for (int i = 0; i < 16; i++) creg[i] = 0.f;
    float sreg[4][2] = {}, ssreg[4][2] = {};
    unsigned mygen = 0;

    const int arow = wr + aoff;
    const uint32_t abase = asb + arow * 512;
    const int amask = arow & 7;

    for (int t = 0; t < Ld; t++) {
        const long xz = ((long)b * Ld + t) * 256;

        if (t > 0) {
            const __half* Ab = g_th + (((long)b * Ld + (t - 1)) * 256 + n0) * 256;
#pragma unroll
            for (int w = 0; w < 8; w++) {
                int idx = tid + w * 256;
                int r = idx >> 5, s = idx & 31;
                cp16(asb + (r * 128 + ((s ^ (r & 7)) << 2)) * 4,
                     Ab + (long)r * 256 + s * 8);
            }
        }
        CPCOMMIT;
        // Xp (fp16): 64 rows x 256 halves, row stride 264
#pragma unroll
        for (int w = 0; w < 8; w++) {
            int idx = tid + w * 256;
            int r = idx >> 5, s = idx & 31;
            int gate = s >> 3, ms = (s & 7) * 8;
            cp16(xpb + (r * 264 + gate * 64 + ms) * 2,
                 g_xpjh + (xz + n0 + r) * 1024 + gate * 256 + m0 + ms);
        }
        CPCOMMIT;
        CPWAITG1;
        __syncthreads();

        float acc[16][4] = {};
        if (t > 0) {
#pragma unroll
            for (int j = 0; j < 16; j++) {
                uint32_t af[4];
                ldsm4(af[0], af[1], af[2], af[3],
                      abase + (((j * 2 + aksel) ^ amask) * 16));
#pragma unroll
                for (int np = 0; np < 8; np++) {
                    int col = cbase + np * 16 + boff;
                    uint32_t bf0[2], bf1[2];
                    ldsm4(bf0[0], bf0[1], bf1[0], bf1[1],
                          bsb + col * 512 + (((j * 2 + bksel) ^ (col & 7)) * 16));
                    mma_f16(acc[2 * np], af, bf0);
                    mma_f16(acc[2 * np + 1], af, bf1);
                }
            }
        }
        CPWAIT0;
        __syncthreads();

#pragma unroll
        for (int ni2 = 0; ni2 < 4; ni2++) {
            const int mloc = (wid & 1) * 32 + ni2 * 8 + tq * 2;
#pragma unroll
            for (int rs = 0; rs < 2; rs++) {
                const int lr2 = rs ? r1 : r0;
                const __half* xr = Xp + lr2 * 264 + mloc;
                float2 xi2 = __half22float2(*(const __half2*)(xr));
                float2 xf2 = __half22float2(*(const __half2*)(xr + 64));
                float2 xg2 = __half22float2(*(const __half2*)(xr + 128));
                float2 xo2 = __half22float2(*(const __half2*)(xr + 192));
                float hv[2];
#pragma unroll
                for (int col = 0; col < 2; col++) {
                    int ai = rs * 2 + col;
                    float zi = acc[ni2][ai] + (col ? xi2.y : xi2.x);
                    float zf = acc[4 + ni2][ai] + (col ? xf2.y : xf2.x);
                    float zg = acc[8 + ni2][ai] + (col ? xg2.y : xg2.x);
                    float zo = acc[12 + ni2][ai] + (col ? xo2.y : xo2.x);
                    int k = ni2 * 4 + ai;
                    float cc = sigf(zf) * creg[k] + sigf(zi) * tanhf(zg);
                    creg[k] = cc;
                    float h = sigf(zo) * tanhf(cc);
                    float hr = __half2float(__float2half_rn(h));
                    sreg[ni2][col] += hr;
                    ssreg[ni2][col] += hr * hr;
                    hv[col] = h;
                }
                *(uint32_t*)&g_th[(xz + n0 + lr2) * 256 + m0 + mloc] = pack2(hv[0], hv[1]);
            }
        }
        if (t < Ld - 1) rgbar(rg, mygen);
    }

    // ---- BN stats reduction: block-local smem then global atomics ----
    __syncthreads();
    float* red = (float*)As;
    for (int i = tid; i < 128; i += 256) red[i] = 0.f;
    __syncthreads();
#pragma unroll
    for (int ni2 = 0; ni2 < 4; ni2++) {
#pragma unroll
        for (int col = 0; col < 2; col++) {
            int ml = (wid & 1) * 32 + ni2 * 8 + tq * 2 + col;
            atomicAdd(&red[ml], sreg[ni2][col]);
            atomicAdd(&red[64 + ml], ssreg[ni2][col]);
        }
    }
    __syncthreads();
    if (tid < 64) {
        atomicAdd(&g_sum[m0 + tid], (double)red[tid]);
        atomicAdd(&g_ssum[m0 + tid], (double)red[64 + tid]);
    }
}

// ---------------- BN finalize -------------------------------------------------
__global__ void k_finalize(const float* __restrict__ gamma, const float* __restrict__ beta) {
    int m = threadIdx.x;
    double mu = g_sum[m] / 65536.0;
    double var = g_ssum[m] / 65536.0 - mu * mu;
    float q = gamma[m] * (float)(1.0 / sqrt(var + 1e-5));
    g_q[m] = q;
    g_r0[m] = beta[m] - (float)mu * q;
}

// ---------------- launch ------------------------------------------------------
extern "C" void kernel_launch(void* const* d_in, const int* in_sizes, int n_in,
                              void* d_out, int out_size) {
    const float* X     = (const float*)d_in[0];
    const float* dis   = (const float*)d_in[1];
    const float* E1    = (const float*)d_in[2];
    const float* E2    = (const float*)d_in[3];
    const float* W_ih  = (const float*)d_in[4];
    const float* W_hh  = (const float*)d_in[5];
    const float* b_ih  = (const float*)d_in[6];
    const float* b_hh  = (const float*)d_in[7];
    const float* gamma = (const float*)d_in[8];
    const float* beta  = (const float*)d_in[9];
    const float* W_lin = (const float*)d_in[10];
    const float* b_lin = (const float*)d_in[11];
    float* out = (float*)d_out;

    const int GSMEM = 3 * 32768;                                   // 98304 B
    const int LSMEM = (256 * 128 + 64 * 128) * 4 + 64 * 264 * 2;   // 197632 B

    cudaFuncSetAttribute(kh<0, 0, 1>, cudaFuncAttributeMaxDynamicSharedMemorySize, GSMEM);
    cudaFuncSetAttribute(kh<1, 1, 1>, cudaFuncAttributeMaxDynamicSharedMemorySize, GSMEM);
    cudaFuncSetAttribute(kh<0, 1, 1>, cudaFuncAttributeMaxDynamicSharedMemorySize, GSMEM);
    cudaFuncSetAttribute(kh<0, 0, 0>, cudaFuncAttributeMaxDynamicSharedMemorySize, GSMEM);
    cudaFuncSetAttribute(k_lstm, cudaFuncAttributeMaxDynamicSharedMemorySize, LSMEM);

    __half *pXh, *pXwh, *pEch, *pWihh, *pWlinh, *pFch, *pTbh, *pPrh, *pXpjh;
    float *pBiasz;
    cudaGetSymbolAddress((void**)&pXh, g_Xh);
    cudaGetSymbolAddress((void**)&pXwh, g_Xwh);
    cudaGetSymbolAddress((void**)&pEch, g_Ech);
    cudaGetSymbolAddress((void**)&pWihh, g_Wihh);
    cudaGetSymbolAddress((void**)&pWlinh, g_Wlinh);
    cudaGetSymbolAddress((void**)&pFch, g_Fch);
    cudaGetSymbolAddress((void**)&pTbh, g_tbh);
    cudaGetSymbolAddress((void**)&pPrh, g_prh);
    cudaGetSymbolAddress((void**)&pXpjh, g_xpjh);
    cudaGetSymbolAddress((void**)&pBiasz, g_biasz);

    k_softmax<<<256, 256>>>(dis, b_ih, b_hh);
    k_prep<<<16384, 256>>>((const float4*)X, (const float4*)E1, (const float4*)E2,
                           (const float4*)W_ih, (const float4*)W_hh, (const float4*)W_lin);

    // Fcat
    kh<0, 0, 1><<<dim3(8, 2, 2), 128, GSMEM>>>(
        pWihh, nullptr, 256, 512, pEch, 65536, 256,
        pFch, 256, 512, nullptr, 256);

    // xproj = [Xh | Xwh] @ Fcat^T + biasz (K=512), fp16 out
    kh<1, 1, 1><<<dim3(2, 8, 256), 128, GSMEM>>>(
        pXh, pXwh, 65536, 256, pFch, 0, 512,
        pXpjh, 262144, 1024, pBiasz, 512);

    // persistent LSTM (row-group barriers, fp16 Xp, fused BN stats)
    k_lstm<<<128, 256, LSMEM>>>();

    k_finalize<<<1, 256>>>(gamma, beta);
    k_affine<<<32768, 256>>>();

    // proj = tb @ Wlin^T + b_lin (half out)
    kh<0, 1, 1><<<dim3(2, 2, 256), 128, GSMEM>>>(
        pTbh, nullptr, 65536, 256, pWlinh, 0, 256,
        pPrh, 65536, 256, b_lin, 256);

    // out = proj @ tb^T (fp32 out)
    kh<0, 0, 0><<<dim3(2, 2, 256), 128, GSMEM>>>(
        pPrh, nullptr, 65536, 256, pTbh, 65536, 256,
        out, 65536, 256, nullptr, 256);
}

// round 17
// speedup vs baseline: 1.2609x; 1.0280x over previous
#include <cuda_runtime.h>
#include <cuda_fp16.h>
#include <cstdint>
#include <math.h>

#define Bd 8
#define Ld 32
#define HN ((size_t)Bd * Ld * 256 * 256)   // 16777216

// ---------------- device scratch ------------------------------------------
__device__ __align__(16) float g_w[256 * 256];
__device__ __align__(16) __half g_Xh[HN];
__device__ __align__(16) __half g_Xwh[HN];
__device__ __align__(16) __half g_Ech[2 * 256 * 256];
__device__ __align__(16) __half g_Wihh[1024 * 512];
__device__ __align__(16) __half g_Wlinh[256 * 256];  // scaled in-place by k_wprep
__device__ __align__(16) __half g_Whrh[1024 * 256];
__device__ __align__(16) __half g_Fch[1024 * 512];
__device__ __align__(16) __half g_th[HN];      // LSTM h
__device__ __align__(16) __half g_prh[HN];     // projq = proj*q (fp16)
__device__ __align__(16) __half g_xpjh[HN * 4];// xproj (fp16)
__device__ __align__(16) float g_biasz[1024];
__device__ __align__(16) float g_srow[256 * 256];  // per-(z,row) s term
__device__ float g_c0[256];
__device__ double g_sum[256], g_ssum[256];
__device__ float g_q[256], g_r0[256];
// per-row-group barrier state, 128B padded per group
__device__ unsigned g_rgc[32 * 32];
__device__ volatile unsigned g_rgg[32 * 32];

// ---------------- helpers --------------------------------------------------
__device__ __forceinline__ uint32_t pack2(float a, float b) {
    __half2 h = __floats2half2_rn(a, b);
    return *(uint32_t*)&h;
}
__device__ __forceinline__ void mma_f16(float* d, const uint32_t* a, const uint32_t* b) {
    asm volatile(
        "mma.sync.aligned.m16n8k16.row.col.f32.f16.f16.f32 "
        "{%0,%1,%2,%3}, {%4,%5,%6,%7}, {%8,%9}, {%0,%1,%2,%3};\n"
        : "+f"(d[0]), "+f"(d[1]), "+f"(d[2]), "+f"(d[3])
        : "r"(a[0]), "r"(a[1]), "r"(a[2]), "r"(a[3]), "r"(b[0]), "r"(b[1]));
}
__device__ __forceinline__ void ldsm4(uint32_t& r0, uint32_t& r1, uint32_t& r2,
                                      uint32_t& r3, uint32_t addr) {
    asm volatile("ldmatrix.sync.aligned.m8n8.x4.shared.b16 {%0,%1,%2,%3}, [%4];"
                 : "=r"(r0), "=r"(r1), "=r"(r2), "=r"(r3) : "r"(addr));
}
__device__ __forceinline__ float sigf(float x) { return 1.f / (1.f + expf(-x)); }

__device__ __forceinline__ void cp16(uint32_t s, const void* g) {
    asm volatile("cp.async.cg.shared.global [%0], [%1], 16;" :: "r"(s), "l"(g));
}
#define CPCOMMIT asm volatile("cp.async.commit_group;")
#define CPWAIT2 asm volatile("cp.async.wait_group 2;")
#define CPWAIT1 asm volatile("cp.async.wait_group 1;")
#define CPWAIT0 asm volatile("cp.async.wait_group 0;")

// ---------------- softmax + init (merged) ------------------------------------
__global__ void k_softmax(const float* __restrict__ dis, const float* __restrict__ bih,
                          const float* __restrict__ bhh) {
    __shared__ float red[256];
    int o = blockIdx.x, t = threadIdx.x;
    float e = expf(-dis[o * 256 + t]);
    red[t] = e;
    if (o < 4) {
        int i = o * 256 + t;
        g_biasz[i] = bih[i] + bhh[i];
        if (i < 256) { g_sum[i] = 0.0; g_ssum[i] = 0.0; }
        g_rgc[i] = 0;
        g_rgg[i] = 0;
    }
    __syncthreads();
    for (int s = 128; s > 0; s >>= 1) {
        if (t < s) red[t] += red[t + s];
        __syncthreads();
    }
    g_w[o * 256 + t] = e / red[0];
}

// ---------------- prep: fp16 operand copies + srow zero ----------------------
__global__ void k_prep(const float4* __restrict__ X, const float4* __restrict__ E1,
                       const float4* __restrict__ E2, const float4* __restrict__ W_ih,
                       const float4* __restrict__ W_hh, const float4* __restrict__ W_lin) {
    long i = (long)blockIdx.x * 256 + threadIdx.x;  // grid 16384
    int nd = (int)(i & 16383);
    float4 x = X[i];
    float4 w = ((const float4*)g_w)[nd];
    ((uint2*)g_Xh)[i] = make_uint2(pack2(x.x, x.y), pack2(x.z, x.w));
    ((uint2*)g_Xwh)[i] = make_uint2(pack2(x.x * w.x, x.y * w.y), pack2(x.z * w.z, x.w * w.w));
    if (i < 32768) {
        float4 e = (i < 16384) ? E1[i] : E2[i - 16384];
        ((uint2*)g_Ech)[i] = make_uint2(pack2(e.x, e.y), pack2(e.z, e.w));
    }
    if (i < 131072) {
        float4 v = W_ih[i];
        ((uint2*)g_Wihh)[i] = make_uint2(pack2(v.x, v.y), pack2(v.z, v.w));
    }
    if (i < 65536) {
        float4 v = W_hh[i];
        ((uint2*)g_Whrh)[i] = make_uint2(pack2(v.x, v.y), pack2(v.z, v.w));
    }
    if (i < 16384) {
        float4 v = W_lin[i];
        ((uint2*)g_Wlinh)[i] = make_uint2(pack2(v.x, v.y), pack2(v.z, v.w));
        ((float4*)g_srow)[i] = make_float4(0.f, 0.f, 0.f, 0.f);
    }
}

// ---------------- 128x128 fp16 GEMM, ldmatrix, 3-stage cp.async --------------
// HB: 0 none, 1 col-bias, 2 row-bias (indexed per z). OH: half output.
// PE: proj epilogue — v += bias[col]; store half(v*q[col]); srow[z,row] += v*r0[col].
template <int AHALF, int HB, int OH, int PE>
__global__ void __launch_bounds__(128, 2) kh(
    const __half* __restrict__ A, const __half* __restrict__ A2, long sA, int lda,
    const __half* __restrict__ Bt, long sB, int ldb,
    void* __restrict__ C, long sC, int ldc,
    const float* __restrict__ bias,
    const float* __restrict__ qv, const float* __restrict__ r0v,
    float* __restrict__ srow, int K) {
    extern __shared__ uint32_t smu[];
    const uint32_t sbase = (uint32_t)__cvta_generic_to_shared(smu);

    const int tid = threadIdx.x;
    const int z = blockIdx.z;
    const __half* Ab = A + sA * z;
    const __half* Ab2 = AHALF ? (A2 + sA * z) : nullptr;
    const __half* Bb = Bt + sB * z;
    float* Cf = OH ? nullptr : ((float*)C + sC * z);
    __half* Ch = OH ? ((__half*)C + sC * z) : nullptr;
    const int row0 = blockIdx.x * 128, col0 = blockIdx.y * 128;
    const float* brow = (HB == 2) ? (bias + (long)z * 256) : nullptr;
    float* srz = PE ? (srow + (long)z * 256) : nullptr;

    const int lane = tid & 31, wid = tid >> 5;
    const int wm = (wid >> 1) * 64, wn = (wid & 1) * 64;
    const int g = lane >> 2, tq = lane & 3;
    const int rL = tid >> 3, sec = tid & 7;
    const int nk = K / 64;

    const int g2 = lane >> 3, lr = lane & 7;
    const int aoff = (g2 & 1) * 8 + lr, aksel = g2 >> 1;
    const int boff = (g2 >> 1) * 8 + lr, bksel = g2 & 1;

    auto load = [&](int stg, int k0) {
        const __half* Asrc;
        int kc;
        if (AHALF && k0 >= 256) { Asrc = Ab2; kc = k0 - 256 + sec * 8; }
        else { Asrc = Ab; kc = k0 + sec * 8; }
        uint32_t ab = sbase + stg * 32768;
        uint32_t bb = ab + 16384;
#pragma unroll
        for (int i = 0; i < 8; i++) {
            int r = rL + i * 16;
            cp16(ab + r * 128 + ((sec ^ (r & 7)) * 16),
                 Asrc + (long)(row0 + r) * lda + kc);
        }
#pragma unroll
        for (int i = 0; i < 8; i++) {
            int r = rL + i * 16;
            cp16(bb + r * 128 + ((sec ^ (r & 7)) * 16),
                 Bb + (long)(col0 + r) * ldb + k0 + sec * 8);
        }
        CPCOMMIT;
    };

    float acc[4][8][4] = {};
    load(0, 0);
    load(1, 64);
    for (int kt = 0; kt < nk; kt++) {
        if (kt + 2 < nk) { load((kt + 2) % 3, (kt + 2) * 64); CPWAIT2; }
        else if (kt + 1 < nk) { CPWAIT1; }
        else { CPWAIT0; }
        __syncthreads();
        const uint32_t ab = sbase + (kt % 3) * 32768;
        const uint32_t bb = ab + 16384;
#pragma unroll
        for (int kw = 0; kw < 4; kw++) {
            uint32_t af[4][4], bf[8][2];
#pragma unroll
            for (int mi = 0; mi < 4; mi++) {
                int rr = wm + mi * 16 + aoff;
                uint32_t addr = ab + rr * 128 + (((kw * 2 + aksel) ^ lr) * 16);
                ldsm4(af[mi][0], af[mi][1], af[mi][2], af[mi][3], addr);
            }
#pragma unroll
            for (int np = 0; np < 4; np++) {
                int rr = wn + np * 16 + boff;
                uint32_t addr = bb + rr * 128 + (((kw * 2 + bksel) ^ lr) * 16);
                ldsm4(bf[2 * np][0], bf[2 * np][1], bf[2 * np + 1][0], bf[2 * np + 1][1], addr);
            }
#pragma unroll
            for (int mi = 0; mi < 4; mi++)
#pragma unroll
                for (int ni = 0; ni < 8; ni++) mma_f16(acc[mi][ni], af[mi], bf[ni]);
        }
        __syncthreads();
    }
#pragma unroll
    for (int mi = 0; mi < 4; mi++) {
        int rr = row0 + wm + mi * 16 + g;
        float rs0 = 0.f, rs1 = 0.f;
        float br0 = (HB == 2) ? brow[rr] : 0.f;
        float br1 = (HB == 2) ? brow[rr + 8] : 0.f;
#pragma unroll
        for (int ni = 0; ni < 8; ni++) {
            int cc = col0 + wn + ni * 8 + tq * 2;
            float b0 = (HB == 1) ? bias[cc] : br0;
            float b1 = (HB == 1) ? bias[cc + 1] : br0;
            float b2 = (HB == 1) ? bias[cc] : br1;
            float b3 = (HB == 1) ? bias[cc + 1] : br1;
            float v0 = acc[mi][ni][0] + b0, v1 = acc[mi][ni][1] + b1;
            float v2 = acc[mi][ni][2] + b2, v3 = acc[mi][ni][3] + b3;
            if (PE) {
                float q0 = qv[cc], q1 = qv[cc + 1];
                float r0c = r0v[cc], r1c = r0v[cc + 1];
                rs0 += v0 * r0c + v1 * r1c;
                rs1 += v2 * r0c + v3 * r1c;
                *(uint32_t*)&Ch[(long)rr * ldc + cc] = pack2(v0 * q0, v1 * q1);
                *(uint32_t*)&Ch[(long)(rr + 8) * ldc + cc] = pack2(v2 * q0, v3 * q1);
            } else if (OH) {
                *(uint32_t*)&Ch[(long)rr * ldc + cc] = pack2(v0, v1);
                *(uint32_t*)&Ch[(long)(rr + 8) * ldc + cc] = pack2(v2, v3);
            } else {
                Cf[(long)rr * ldc + cc] = v0;
                Cf[(long)rr * ldc + cc + 1] = v1;
                Cf[(long)(rr + 8) * ldc + cc] = v2;
                Cf[(long)(rr + 8) * ldc + cc + 1] = v3;
            }
        }
        if (PE) {
            rs0 += __shfl_xor_sync(0xffffffffu, rs0, 1);
            rs0 += __shfl_xor_sync(0xffffffffu, rs0, 2);
            rs1 += __shfl_xor_sync(0xffffffffu, rs1, 1);
            rs1 += __shfl_xor_sync(0xffffffffu, rs1, 2);
            if (tq == 0) {
                atomicAdd(&srz[rr], rs0);
                atomicAdd(&srz[rr + 8], rs1);
            }
        }
    }
}

// ---------------- row-group barrier (4 blocks, 128B-padded state) ------------
__device__ __forceinline__ void rgbar(int rg, unsigned& mygen) {
    __syncthreads();
    if (threadIdx.x == 0) {
        __threadfence();
        unsigned* cnt = &g_rgc[rg * 32];
        volatile unsigned* gen = &g_rgg[rg * 32];
        unsigned old = atomicAdd(cnt, 1u);
        if (old == 3u) {
            *cnt = 0;
            __threadfence();
            atomicAdd((unsigned*)gen, 1u);
        } else {
            while (*gen <= mygen) {}
        }
        __threadfence();
    }
    __syncthreads();
    mygen++;
}

// ---------------- persistent LSTM: 2-phase A pipeline ------------------------
__global__ void __launch_bounds__(256) k_lstm() {
    extern __shared__ uint32_t smL[];
    uint32_t* Bs = smL;                           // 256 x 128 u32 (swizzled)
    uint32_t* As = smL + 256 * 128;               // 64 x 128 u32 (swizzled)
    __half* Xp = (__half*)(smL + 256 * 128 + 64 * 128);  // 64 x 264 half

    const int tid = threadIdx.x;
    const int bid = blockIdx.x;
    const int rg = bid >> 2;
    const int rows0 = rg * 64, m0 = (bid & 3) * 64;
    const int b = rows0 >> 8, n0 = rows0 & 255;
    const int lane = tid & 31, wid = tid >> 5;
    const int g = lane >> 2, tq = lane & 3;
    const int wr = (wid >> 1) * 16;
    const int cbase = (wid & 1) * 128;
    const int r0 = wr + g, r1 = wr + g + 8;

    const int g2 = lane >> 3, lr = lane & 7;
    const int aoff = (g2 & 1) * 8 + lr, aksel = g2 >> 1;
    const int boff = (g2 >> 1) * 8 + lr, bksel = g2 & 1;

    const uint32_t bsb = (uint32_t)__cvta_generic_to_shared(Bs);
    const uint32_t asb = (uint32_t)__cvta_generic_to_shared(As);
    const uint32_t xpb = (uint32_t)__cvta_generic_to_shared(Xp);

    // ---- preload gathered Whh slice (once) ----
#pragma unroll
    for (int w = 0; w < 32; w++) {
        int idx = tid + w * 256;
        int c = idx >> 5, s = idx & 31;
        int n = c & 127, nw = c >> 7;
        int wrow = (n >> 5) * 256 + m0 + nw * 32 + (n & 31);
        cp16(bsb + (c * 128 + ((s ^ (c & 7)) << 2)) * 4,
             g_Whrh + (long)wrow * 256 + s * 8);
    }
    CPCOMMIT; CPWAIT0;
    __syncthreads();

    float creg[16];
#pragma unroll
    for (int i = 0; i < 16; i++) creg[i] = 0.f;
    float sreg[4][2] = {}, ssreg[4][2] = {};
    unsigned mygen = 0;

    const int arow = wr + aoff;
    const uint32_t abase = asb + arow * 512;
    const int amask = arow & 7;

    for (int t = 0; t < Ld; t++) {
        const long xz = ((long)b * Ld + t) * 256;

        if (t > 0) {
            const __half* Ab = g_th + (((long)b * Ld + (t - 1)) * 256 + n0) * 256;
            // A half 0 (K 0..127): sectors 0..15
#pragma unroll
            for (int w = 0; w < 4; w++) {
                int idx = tid + w * 256;
                int r = idx >> 4, s = idx & 15;
                cp16(asb + (r * 128 + ((s ^ (r & 7)) << 2)) * 4,
                     Ab + (long)r * 256 + s * 8);
            }
            CPCOMMIT;
            // A half 1 (K 128..255): sectors 16..31
#pragma unroll
            for (int w = 0; w < 4; w++) {
                int idx = tid + w * 256;
                int r = idx >> 4, s = (idx & 15) + 16;
                cp16(asb + (r * 128 + ((s ^ (r & 7)) << 2)) * 4,
                     Ab + (long)r * 256 + s * 8);
            }
            CPCOMMIT;
        }
        // Xp (fp16): 64 rows x 256 halves, row stride 264
#pragma unroll
        for (int w = 0; w < 8; w++) {
            int idx = tid + w * 256;
            int r = idx >> 5, s = idx & 31;
            int gate = s >> 3, ms = (s & 7) * 8;
            cp16(xpb + (r * 264 + gate * 64 + ms) * 2,
                 g_xpjh + (xz + n0 + r) * 1024 + gate * 256 + m0 + ms);
        }
        CPCOMMIT;

        float acc[16][4] = {};
        if (t > 0) {
            CPWAIT2;                    // A half 0 arrived
            __syncthreads();
#pragma unroll
            for (int j = 0; j < 8; j++) {
                uint32_t af[4];
                ldsm4(af[0], af[1], af[2], af[3],
                      abase + (((j * 2 + aksel) ^ amask) * 16));
#pragma unroll
                for (int np = 0; np < 8; np++) {
                    int col = cbase + np * 16 + boff;
                    uint32_t bf0[2], bf1[2];
                    ldsm4(bf0[0], bf0[1], bf1[0], bf1[1],
                          bsb + col * 512 + (((j * 2 + bksel) ^ (col & 7)) * 16));
                    mma_f16(acc[2 * np], af, bf0);
                    mma_f16(acc[2 * np + 1], af, bf1);
                }
            }
            CPWAIT1;                    // A half 1 arrived
            __syncthreads();
#pragma unroll
            for (int j = 8; j < 16; j++) {
                uint32_t af[4];
                ldsm4(af[0], af[1], af[2], af[3],
                      abase + (((j * 2 + aksel) ^ amask) * 16));
#pragma unroll
                for (int np = 0; np < 8; np++) {
                    int col = cbase + np * 16 + boff;
                    uint32_t bf0[2], bf1[2];
                    ldsm4(bf0[0], bf0[1], bf1[0], bf1[1],
                          bsb + col * 512 + (((j * 2 + bksel) ^ (col & 7)) * 16));
                    mma_f16(acc[2 * np], af, bf0);
                    mma_f16(acc[2 * np + 1], af, bf1);
                }
            }
        }
        CPWAIT0;                        // Xp arrived
        __syncthreads();

#pragma unroll
        for (int ni2 = 0; ni2 < 4; ni2++) {
            const int mloc = (wid & 1) * 32 + ni2 * 8 + tq * 2;
#pragma unroll
            for (int rs = 0; rs < 2; rs++) {
                const int lr2 = rs ? r1 : r0;
                const __half* xr = Xp + lr2 * 264 + mloc;
                float2 xi2 = __half22float2(*(const __half2*)(xr));
                float2 xf2 = __half22float2(*(const __half2*)(xr + 64));
                float2 xg2 = __half22float2(*(const __half2*)(xr + 128));
                float2 xo2 = __half22float2(*(const __half2*)(xr + 192));
                float hv[2];
#pragma unroll
                for (int col = 0; col < 2; col++) {
                    int ai = rs * 2 + col;
                    float zi = acc[ni2][ai] + (col ? xi2.y : xi2.x);
                    float zf = acc[4 + ni2][ai] + (col ? xf2.y : xf2.x);
                    float zg = acc[8 + ni2][ai] + (col ? xg2.y : xg2.x);
                    float zo = acc[12 + ni2][ai] + (col ? xo2.y : xo2.x);
                    int k = ni2 * 4 + ai;
                    float cc = sigf(zf) * creg[k] + sigf(zi) * tanhf(zg);
                    creg[k] = cc;
                    float h = sigf(zo) * tanhf(cc);
                    float hr = __half2float(__float2half_rn(h));
                    sreg[ni2][col] += hr;
                    ssreg[ni2][col] += hr * hr;
                    hv[col] = h;
                }
                *(uint32_t*)&g_th[(xz + n0 + lr2) * 256 + m0 + mloc] = pack2(hv[0], hv[1]);
            }
        }
        if (t < Ld - 1) rgbar(rg, mygen);
    }

    // ---- BN stats reduction ----
    __syncthreads();
    float* red = (float*)As;
    for (int i = tid; i < 128; i += 256) red[i] = 0.f;
    __syncthreads();
#pragma unroll
    for (int ni2 = 0; ni2 < 4; ni2++) {
#pragma unroll
        for (int col = 0; col < 2; col++) {
            int ml = (wid & 1) * 32 + ni2 * 8 + tq * 2 + col;
            atomicAdd(&red[ml], sreg[ni2][col]);
            atomicAdd(&red[64 + ml], ssreg[ni2][col]);
        }
    }
    __syncthreads();
    if (tid < 64) {
        atomicAdd(&g_sum[m0 + tid], (double)red[tid]);
        atomicAdd(&g_ssum[m0 + tid], (double)red[64 + tid]);
    }
}

// ---------------- BN finalize -------------------------------------------------
__global__ void k_finalize(const float* __restrict__ gamma, const float* __restrict__ beta) {
    int m = threadIdx.x;
    double mu = g_sum[m] / 65536.0;
    double var = g_ssum[m] / 65536.0 - mu * mu;
    float q = gamma[m] * (float)(1.0 / sqrt(var + 1e-5));
    g_q[m] = q;
    g_r0[m] = beta[m] - (float)mu * q;
}

// ---------------- wprep: Wlin <- q*Wlin (in place); c0 = Wlin@r0 + b_lin ------
__global__ void k_wprep(const float* __restrict__ b_lin) {
    __shared__ float red[256];
    int j = blockIdx.x, m = threadIdx.x;
    float wv = __half2float(g_Wlinh[j * 256 + m]);
    red[m] = g_r0[m] * wv;
    g_Wlinh[j * 256 + m] = __float2half_rn(g_q[m] * wv);
    __syncthreads();
    for (int s = 128; s > 0; s >>= 1) {
        if (m < s) red[m] += red[m + s];
        __syncthreads();
    }
    if (m == 0) g_c0[j] = red[0] + b_lin[j];
}

// ---------------- launch ------------------------------------------------------
extern "C" void kernel_launch(void* const* d_in, const int* in_sizes, int n_in,
                              void* d_out, int out_size) {
    const float* X     = (const float*)d_in[0];
    const float* dis   = (const float*)d_in[1];
    const float* E1    = (const float*)d_in[2];
    const float* E2    = (const float*)d_in[3];
    const float* W_ih  = (const float*)d_in[4];
    const float* W_hh  = (const float*)d_in[5];
    const float* b_ih  = (const float*)d_in[6];
    const float* b_hh  = (const float*)d_in[7];
    const float* gamma = (const float*)d_in[8];
    const float* beta  = (const float*)d_in[9];
    const float* W_lin = (const float*)d_in[10];
    const float* b_lin = (const float*)d_in[11];
    float* out = (float*)d_out;

    const int GSMEM = 3 * 32768;                                   // 98304 B
    const int LSMEM = (256 * 128 + 64 * 128) * 4 + 64 * 264 * 2;   // 197632 B

    cudaFuncSetAttribute(kh<0, 0, 1, 0>, cudaFuncAttributeMaxDynamicSharedMemorySize, GSMEM);
    cudaFuncSetAttribute(kh<1, 1, 1, 0>, cudaFuncAttributeMaxDynamicSharedMemorySize, GSMEM);
    cudaFuncSetAttribute(kh<0, 1, 1, 1>, cudaFuncAttributeMaxDynamicSharedMemorySize, GSMEM);
    cudaFuncSetAttribute(kh<0, 2, 0, 0>, cudaFuncAttributeMaxDynamicSharedMemorySize, GSMEM);
    cudaFuncSetAttribute(k_lstm, cudaFuncAttributeMaxDynamicSharedMemorySize, LSMEM);

    __half *pXh, *pXwh, *pEch, *pWihh, *pWlinh, *pFch, *pTh, *pPrh, *pXpjh;
    float *pBiasz, *pC0, *pQ, *pR0, *pSrow;
    cudaGetSymbolAddress((void**)&pXh, g_Xh);
    cudaGetSymbolAddress((void**)&pXwh, g_Xwh);
    cudaGetSymbolAddress((void**)&pEch, g_Ech);
    cudaGetSymbolAddress((void**)&pWihh, g_Wihh);
    cudaGetSymbolAddress((void**)&pWlinh, g_Wlinh);
    cudaGetSymbolAddress((void**)&pFch, g_Fch);
    cudaGetSymbolAddress((void**)&pTh, g_th);
    cudaGetSymbolAddress((void**)&pPrh, g_prh);
    cudaGetSymbolAddress((void**)&pXpjh, g_xpjh);
    cudaGetSymbolAddress((void**)&pBiasz, g_biasz);
    cudaGetSymbolAddress((void**)&pC0, g_c0);
    cudaGetSymbolAddress((void**)&pQ, g_q);
    cudaGetSymbolAddress((void**)&pR0, g_r0);
    cudaGetSymbolAddress((void**)&pSrow, g_srow);

    k_softmax<<<256, 256>>>(dis, b_ih, b_hh);
    k_prep<<<16384, 256>>>((const float4*)X, (const float4*)E1, (const float4*)E2,
                           (const float4*)W_ih, (const float4*)W_hh, (const float4*)W_lin);

    // Fcat
    kh<0, 0, 1, 0><<<dim3(8, 2, 2), 128, GSMEM>>>(
        pWihh, nullptr, 256, 512, pEch, 65536, 256,
        pFch, 256, 512, nullptr, nullptr, nullptr, nullptr, 256);

    // xproj = [Xh | Xwh] @ Fcat^T + biasz (K=512), fp16 out
    kh<1, 1, 1, 0><<<dim3(2, 8, 256), 128, GSMEM>>>(
        pXh, pXwh, 65536, 256, pFch, 0, 512,
        pXpjh, 262144, 1024, pBiasz, nullptr, nullptr, nullptr, 512);

    // persistent LSTM
    k_lstm<<<128, 256, LSMEM>>>();

    k_finalize<<<1, 256>>>(gamma, beta);
    k_wprep<<<256, 256>>>(b_lin);

    // projq = (h @ (q*Wlin)^T + c0) * q[col]; srow += proj*r0  (half out)
    kh<0, 1, 1, 1><<<dim3(2, 2, 256), 128, GSMEM>>>(
        pTh, nullptr, 65536, 256, pWlinh, 0, 256,
        pPrh, 65536, 256, pC0, pQ, pR0, pSrow, 256);

    // out = projq @ h^T + srow[row]  (fp32 out)
    kh<0, 2, 0, 0><<<dim3(2, 2, 256), 128, GSMEM>>>(
        pPrh, nullptr, 65536, 256, pTh, 65536, 256,
        out, 65536, 256, pSrow, nullptr, nullptr, nullptr, 256);
}